// round 2
// baseline (speedup 1.0000x reference)
#include <cuda_runtime.h>
#include <math.h>

#define BB 64
#define LL 256
#define HH 16
#define COMBC 770
#define DMODEL 1282
#define DINNER 2564
#define DSTATE 16
#define MSEQ (BB*LL)          // 16384
#define DBL_LD 116            // padded row for dbl: dt[0..80], B at 84..99, C at 100..115

// ---------------- scratch (device globals; no allocations allowed) ----------------
__device__ float g_seq[(size_t)MSEQ * DMODEL];        // (b*256+l, 1282)
__device__ float g_tmp0[(size_t)MSEQ * 128];          // cbr0 full-res output
__device__ float g_y0[BB * 128];                      // pooled-to-1 branch
__device__ float g_pooled[(size_t)17600 * COMBC];     // scale-major pooled comb rows
__device__ float g_yp[(size_t)17600 * 128];           // cbr outputs at pooled res
__device__ float g_xz[(size_t)MSEQ * 2 * DINNER];     // in_proj output
__device__ float g_u[(size_t)MSEQ * DINNER];          // conv1d+silu output
__device__ float g_dbl[(size_t)MSEQ * DBL_LD];        // x_proj output (remapped cols)
__device__ float g_dtv[(size_t)MSEQ * DINNER];        // softplus(dt)
__device__ float g_ys[(size_t)MSEQ * DINNER];         // scan output * silu(z)
__device__ float g_bn[1024];                          // [0:512) inv, [512:1024) add

// ---------------- BN param prep ----------------
__global__ void k_bnprep(const float* __restrict__ gamma, const float* __restrict__ beta,
                         const float* __restrict__ mean, const float* __restrict__ var) {
    int i = threadIdx.x;  // 512
    if (i < 512) {
        float inv = rsqrtf(var[i] + 1e-5f) * gamma[i];
        g_bn[i] = inv;
        g_bn[512 + i] = beta[i] - mean[i] * inv;
    }
}

// ---------------- build comb into seq[:, 0:770] (tiled transpose) ----------------
__device__ __forceinline__ float xx_val(int i) { return -0.3f + (0.6f / 15.0f) * (float)i; }

__global__ void k_build(const float* __restrict__ x, const float* __restrict__ pc) {
    __shared__ float tile[32][33];
    int b = blockIdx.x;
    int c0 = blockIdx.y * 32;   // 25 tiles along c (800 >= 770)
    int l0 = blockIdx.z * 32;   // 8 tiles along l
    int tx = threadIdx.x, ty = threadIdx.y;
    // read: (c = c0+ty, l = l0+tx) -- coalesced over l for x
    int c = c0 + ty, l = l0 + tx;
    if (c < COMBC) {
        float v;
        if (c < 512)       v = x[((size_t)(b * 512 + c)) * 256 + l];
        else if (c == 512) v = xx_val(l & 15);       // X-grid: xx[w]
        else if (c == 513) v = xx_val(l >> 4);       // Y-grid: xx[h]
        else               v = pc[b * 256 + (c - 514)];
        tile[ty][tx] = v;
    }
    __syncthreads();
    // write: (c = c0+tx, l = l0+ty) -- coalesced over c for seq
    c = c0 + tx; l = l0 + ty;
    if (c < COMBC)
        g_seq[((size_t)(b * 256 + l)) * DMODEL + c] = tile[tx][ty];
}

// ---------------- generic SGEMM: C[m,n] = sum_k A[m,k]*B[n,k] ----------------
// EP: 0 plain, 1 BN+ReLU6, 2 bias+softplus, 3 transposed store to (b,c,l), 4 remap cols (x_proj)
template<int EP>
__global__ __launch_bounds__(256, 2) void sgemm(
    const float* __restrict__ A, const float* __restrict__ B, float* __restrict__ C,
    int M, int N, int K, int lda, int ldb, int ldc,
    const float* __restrict__ aux1, const float* __restrict__ aux2)
{
    __shared__ float As[8][128];
    __shared__ float Bs[8][128];
    const int tid = threadIdx.x;
    const int tx = tid & 15, ty = tid >> 4;
    const int row0 = blockIdx.y * 128, col0 = blockIdx.x * 128;
    const int lm = tid >> 1;
    const int lk = (tid & 1) * 4;
    float acc[8][8];
#pragma unroll
    for (int i = 0; i < 8; i++)
#pragma unroll
        for (int j = 0; j < 8; j++) acc[i][j] = 0.f;

    const int gmA = row0 + lm;
    const int gnB = col0 + lm;
    for (int k0 = 0; k0 < K; k0 += 8) {
#pragma unroll
        for (int j = 0; j < 4; j++) {
            int gk = k0 + lk + j;
            As[lk + j][lm] = (gmA < M && gk < K) ? A[(size_t)gmA * lda + gk] : 0.f;
            Bs[lk + j][lm] = (gnB < N && gk < K) ? B[(size_t)gnB * ldb + gk] : 0.f;
        }
        __syncthreads();
#pragma unroll
        for (int kk = 0; kk < 8; kk++) {
            float a[8], bb[8];
#pragma unroll
            for (int i = 0; i < 8; i++) a[i] = As[kk][ty * 8 + i];
#pragma unroll
            for (int j = 0; j < 8; j++) bb[j] = Bs[kk][tx * 8 + j];
#pragma unroll
            for (int i = 0; i < 8; i++)
#pragma unroll
                for (int j = 0; j < 8; j++) acc[i][j] = fmaf(a[i], bb[j], acc[i][j]);
        }
        __syncthreads();
    }
#pragma unroll
    for (int i = 0; i < 8; i++) {
        int gm = row0 + ty * 8 + i;
        if (gm >= M) continue;
#pragma unroll
        for (int j = 0; j < 8; j++) {
            int gn = col0 + tx * 8 + j;
            if (gn >= N) continue;
            float v = acc[i][j];
            if (EP == 0) {
                C[(size_t)gm * ldc + gn] = v;
            } else if (EP == 1) {
                v = v * aux1[gn] + aux2[gn];
                v = fminf(fmaxf(v, 0.f), 6.f);
                C[(size_t)gm * ldc + gn] = v;
            } else if (EP == 2) {
                v += aux1[gn];
                v = (v > 20.f) ? v : log1pf(__expf(v));
                C[(size_t)gm * ldc + gn] = v;
            } else if (EP == 3) {
                C[((size_t)(gm >> 8) * DMODEL + gn) * 256 + (gm & 255)] = v;
            } else {
                int cc = (gn < 81) ? gn : gn + 3;
                C[(size_t)gm * DBL_LD + cc] = v;
            }
        }
    }
}

// ---------------- y0 = mean over L of tmp0 ----------------
__global__ void k_reduce0() {
    int b = blockIdx.x, d = threadIdx.x;  // 64 blocks x 128
    float acc = 0.f;
    for (int l = 0; l < 256; l++)
        acc += g_tmp0[((size_t)(b * 256 + l)) * 128 + d];
    g_y0[b * 128 + d] = acc * (1.f / 256.f);
}

// ---------------- adaptive avg pool (16 -> s, s in {5,9,13}) ----------------
__global__ void k_pool() {
    int b = blockIdx.x;
    int spg = blockIdx.y;  // 0..274
    int s, row_base, local;
    if (spg < 25)       { s = 5;  row_base = 0;    local = spg; }
    else if (spg < 106) { s = 9;  row_base = 1600; local = spg - 25; }
    else                { s = 13; row_base = 6784; local = spg - 106; }
    int o = local / s, p = local % s;
    int h0 = (o * 16) / s, h1 = ((o + 1) * 16 + s - 1) / s;
    int w0 = (p * 16) / s, w1 = ((p + 1) * 16 + s - 1) / s;
    float wgt = 1.f / (float)((h1 - h0) * (w1 - w0));
    size_t orow = (size_t)(row_base + b * s * s + local) * COMBC;
    for (int c = threadIdx.x; c < COMBC; c += 256) {
        float acc = 0.f;
        for (int h = h0; h < h1; h++)
            for (int w = w0; w < w1; w++)
                acc += g_seq[((size_t)(b * 256 + h * 16 + w)) * DMODEL + c];
        g_pooled[orow + c] = acc * wgt;
    }
}

// ---------------- assemble seq cols 770..1281 (broadcast y0 + bilinear upsample) ------
__global__ void k_assemble() {
    int m = blockIdx.x;              // 16384
    int b = m >> 8, l = m & 255;
    int o = l >> 4, p = l & 15;
    int t = threadIdx.x;             // 512
    if (t < 128) {
        g_seq[(size_t)m * DMODEL + 770 + t] = g_y0[b * 128 + t];
    } else {
        int i = (t - 128) >> 7;      // 0,1,2 -> scales 5,9,13
        int d = (t - 128) & 127;
        int s      = (i == 0) ? 5 : (i == 1) ? 9 : 13;
        int base_r = (i == 0) ? 0 : (i == 1) ? 1600 : 6784;
        float fs = (float)s;
        float so = (o + 0.5f) * fs / 16.0f - 0.5f;
        so = fminf(fmaxf(so, 0.f), fs - 1.0f);
        int h0 = (int)floorf(so); int h1 = min(h0 + 1, s - 1); float fo = so - (float)h0;
        float sp = (p + 0.5f) * fs / 16.0f - 0.5f;
        sp = fminf(fmaxf(sp, 0.f), fs - 1.0f);
        int w0 = (int)floorf(sp); int w1 = min(w0 + 1, s - 1); float fp = sp - (float)w0;
        const float* yb = g_yp + (size_t)(base_r + b * s * s) * 128 + d;
        float v00 = yb[(size_t)(h0 * s + w0) * 128];
        float v01 = yb[(size_t)(h0 * s + w1) * 128];
        float v10 = yb[(size_t)(h1 * s + w0) * 128];
        float v11 = yb[(size_t)(h1 * s + w1) * 128];
        float v = (1.f - fo) * ((1.f - fp) * v00 + fp * v01)
                + fo * ((1.f - fp) * v10 + fp * v11);
        g_seq[(size_t)m * DMODEL + 898 + i * 128 + d] = v;
    }
}

// ---------------- depthwise causal conv1d + bias + SiLU ----------------
__global__ void k_conv1d(const float* __restrict__ w, const float* __restrict__ bias) {
    int m = blockIdx.x;
    int d = blockIdx.y * 256 + threadIdx.x;
    if (d >= DINNER) return;
    int l = m & 255;
    size_t base = (size_t)m * (2 * DINNER) + d;
    float acc = bias[d];
    const float* wd = w + d * 4;
#pragma unroll
    for (int j = 0; j < 4; j++) {
        int l2 = l - 3 + j;
        if (l2 >= 0) acc += wd[j] * g_xz[base + (size_t)(j - 3) * (2 * DINNER)];
    }
    g_u[(size_t)m * DINNER + d] = acc / (1.f + __expf(-acc));
}

// ---------------- selective scan (one thread per (b,d)) ----------------
__global__ __launch_bounds__(256) void k_scan(const float* __restrict__ A_log,
                                              const float* __restrict__ Dp) {
    int b = blockIdx.y;
    int d = blockIdx.x * 256 + threadIdx.x;
    if (d >= DINNER) return;
    float A[DSTATE];
#pragma unroll
    for (int n = 0; n < DSTATE; n++) A[n] = -__expf(A_log[d * DSTATE + n]);
    float Dd = Dp[d];
    float h[DSTATE];
#pragma unroll
    for (int n = 0; n < DSTATE; n++) h[n] = 0.f;

    const float* dtp = g_dtv + (size_t)b * 256 * DINNER + d;
    const float* up  = g_u   + (size_t)b * 256 * DINNER + d;
    const float* zp  = g_xz  + (size_t)b * 256 * (2 * DINNER) + DINNER + d;
    const float* bc  = g_dbl + (size_t)b * 256 * DBL_LD;
    float* yo        = g_ys  + (size_t)b * 256 * DINNER + d;

    for (int l = 0; l < 256; l++) {
        float dt = dtp[(size_t)l * DINNER];
        float u  = up [(size_t)l * DINNER];
        const float4* bcrow = reinterpret_cast<const float4*>(bc + (size_t)l * DBL_LD + 84);
        float4 Bv0 = bcrow[0], Bv1 = bcrow[1], Bv2 = bcrow[2], Bv3 = bcrow[3];
        float4 Cv0 = bcrow[4], Cv1 = bcrow[5], Cv2 = bcrow[6], Cv3 = bcrow[7];
        float Bm[16] = {Bv0.x,Bv0.y,Bv0.z,Bv0.w, Bv1.x,Bv1.y,Bv1.z,Bv1.w,
                        Bv2.x,Bv2.y,Bv2.z,Bv2.w, Bv3.x,Bv3.y,Bv3.z,Bv3.w};
        float Cm[16] = {Cv0.x,Cv0.y,Cv0.z,Cv0.w, Cv1.x,Cv1.y,Cv1.z,Cv1.w,
                        Cv2.x,Cv2.y,Cv2.z,Cv2.w, Cv3.x,Cv3.y,Cv3.z,Cv3.w};
        float xbu = dt * u;
        float y = 0.f;
#pragma unroll
        for (int n = 0; n < DSTATE; n++) {
            float dA = __expf(dt * A[n]);
            h[n] = dA * h[n] + xbu * Bm[n];
            y += h[n] * Cm[n];
        }
        float z = zp[(size_t)l * (2 * DINNER)];
        float sil = z / (1.f + __expf(-z));
        yo[(size_t)l * DINNER] = (y + u * Dd) * sil;
    }
}

// ---------------- launch ----------------
extern "C" void kernel_launch(void* const* d_in, const int* in_sizes, int n_in,
                              void* d_out, int out_size) {
    (void)in_sizes; (void)n_in; (void)out_size;
    const float* x         = (const float*)d_in[0];
    const float* pc_emb    = (const float*)d_in[1];
    const float* conv_w    = (const float*)d_in[2];
    const float* bn_gamma  = (const float*)d_in[3];
    const float* bn_beta   = (const float*)d_in[4];
    const float* bn_mean   = (const float*)d_in[5];
    const float* bn_var    = (const float*)d_in[6];
    const float* in_proj_w = (const float*)d_in[7];
    const float* conv1d_w  = (const float*)d_in[8];
    const float* conv1d_b  = (const float*)d_in[9];
    const float* x_proj_w  = (const float*)d_in[10];
    const float* dt_proj_w = (const float*)d_in[11];
    const float* dt_proj_b = (const float*)d_in[12];
    const float* A_log     = (const float*)d_in[13];
    const float* Dvec      = (const float*)d_in[14];
    const float* out_proj_w= (const float*)d_in[15];
    float* out = (float*)d_out;

    float *p_seq, *p_tmp0, *p_pooled, *p_yp, *p_xz, *p_u, *p_dbl, *p_dtv, *p_ys, *p_bn;
    cudaGetSymbolAddress((void**)&p_seq,    g_seq);
    cudaGetSymbolAddress((void**)&p_tmp0,   g_tmp0);
    cudaGetSymbolAddress((void**)&p_pooled, g_pooled);
    cudaGetSymbolAddress((void**)&p_yp,     g_yp);
    cudaGetSymbolAddress((void**)&p_xz,     g_xz);
    cudaGetSymbolAddress((void**)&p_u,      g_u);
    cudaGetSymbolAddress((void**)&p_dbl,    g_dbl);
    cudaGetSymbolAddress((void**)&p_dtv,    g_dtv);
    cudaGetSymbolAddress((void**)&p_ys,     g_ys);
    cudaGetSymbolAddress((void**)&p_bn,     g_bn);

    // PPM
    k_bnprep<<<1, 512>>>(bn_gamma, bn_beta, bn_mean, bn_var);
    k_build<<<dim3(64, 25, 8), dim3(32, 32)>>>(x, pc_emb);
    // cbr0 at full res -> tmp0 (BN+ReLU6)
    sgemm<1><<<dim3(1, 128), 256>>>(p_seq, conv_w, p_tmp0,
                                    MSEQ, 128, COMBC, DMODEL, COMBC, 128, p_bn, p_bn + 512);
    k_reduce0<<<64, 128>>>();
    k_pool<<<dim3(64, 275), 256>>>();
    sgemm<1><<<dim3(1, 13), 256>>>(p_pooled, conv_w + 1 * 128 * COMBC, p_yp,
                                   1600, 128, COMBC, COMBC, COMBC, 128,
                                   p_bn + 128, p_bn + 512 + 128);
    sgemm<1><<<dim3(1, 41), 256>>>(p_pooled + (size_t)1600 * COMBC, conv_w + 2 * 128 * COMBC,
                                   p_yp + (size_t)1600 * 128,
                                   5184, 128, COMBC, COMBC, COMBC, 128,
                                   p_bn + 256, p_bn + 512 + 256);
    sgemm<1><<<dim3(1, 85), 256>>>(p_pooled + (size_t)6784 * COMBC, conv_w + 3 * 128 * COMBC,
                                   p_yp + (size_t)6784 * 128,
                                   10816, 128, COMBC, COMBC, COMBC, 128,
                                   p_bn + 384, p_bn + 512 + 384);
    k_assemble<<<MSEQ, 512>>>();

    // Mamba
    sgemm<0><<<dim3(41, 128), 256>>>(p_seq, in_proj_w, p_xz,
                                     MSEQ, 2 * DINNER, DMODEL, DMODEL, DMODEL, 2 * DINNER,
                                     nullptr, nullptr);
    k_conv1d<<<dim3(MSEQ, 11), 256>>>(conv1d_w, conv1d_b);
    sgemm<4><<<dim3(1, 128), 256>>>(p_u, x_proj_w, p_dbl,
                                    MSEQ, 113, DINNER, DINNER, DINNER, DBL_LD,
                                    nullptr, nullptr);
    sgemm<2><<<dim3(21, 128), 256>>>(p_dbl, dt_proj_w, p_dtv,
                                     MSEQ, DINNER, 81, DBL_LD, 81, DINNER,
                                     dt_proj_b, nullptr);
    k_scan<<<dim3(11, 64), 256>>>(A_log, Dvec);
    sgemm<3><<<dim3(11, 128), 256>>>(p_ys, out_proj_w, out,
                                     MSEQ, DMODEL, DINNER, DINNER, DINNER, 0,
                                     nullptr, nullptr);
}

// round 9
// speedup vs baseline: 1.9859x; 1.9859x over previous
#include <cuda_runtime.h>
#include <cuda_bf16.h>
#include <math.h>
#include <stdint.h>

#define BB 64
#define COMBC 770
#define DMODEL 1282
#define DINNER 2564
#define DSTATE 16
#define MSEQ 16384
#define LDSEQ 1312      // padded d_model (41*32)
#define LDYS  2592      // padded d_inner (81*32)
#define DBL_LD 116

// ---------------- scratch (device globals; no allocations allowed) ----------------
__device__ __align__(128) float g_seq[(size_t)MSEQ * LDSEQ];     // padded, pad cols zeroed
__device__ __align__(128) float g_tmp0[(size_t)MSEQ * 128];
__device__ __align__(128) float g_y0[BB * 128];
__device__ __align__(128) float g_pooled[(size_t)17600 * COMBC];
__device__ __align__(128) float g_yp[(size_t)17600 * 128];
__device__ __align__(128) float g_xz[(size_t)MSEQ * 2 * DINNER];
__device__ __align__(128) float g_u[(size_t)MSEQ * DINNER];
__device__ __align__(128) float g_dbl[(size_t)MSEQ * DBL_LD];
__device__ __align__(128) float g_dtv[(size_t)MSEQ * DINNER];
__device__ __align__(128) float g_ys[(size_t)MSEQ * LDYS];       // padded, pad cols zeroed
__device__ __align__(128) float g_bn[1024];

// ================= warp-mma (legacy ISA, bf16 split) GEMM =================
__device__ __forceinline__ uint32_t smem_u32(const void* p) {
    uint32_t a;
    asm("{ .reg .u64 t; cvta.to.shared.u64 t, %1; cvt.u32.u64 %0, t; }" : "=r"(a) : "l"(p));
    return a;
}
__device__ __forceinline__ void ldsm4(uint32_t& r0, uint32_t& r1, uint32_t& r2, uint32_t& r3,
                                      uint32_t addr) {
    asm volatile("ldmatrix.sync.aligned.m8n8.x4.shared.b16 {%0,%1,%2,%3}, [%4];"
                 : "=r"(r0), "=r"(r1), "=r"(r2), "=r"(r3) : "r"(addr));
}
__device__ __forceinline__ void mma_bf16(float* d, const uint32_t* a, const uint32_t* b) {
    asm volatile(
        "mma.sync.aligned.m16n8k16.row.col.f32.bf16.bf16.f32 "
        "{%0,%1,%2,%3}, {%4,%5,%6,%7}, {%8,%9}, {%0,%1,%2,%3};"
        : "+f"(d[0]), "+f"(d[1]), "+f"(d[2]), "+f"(d[3])
        : "r"(a[0]), "r"(a[1]), "r"(a[2]), "r"(a[3]), "r"(b[0]), "r"(b[1]));
}
__device__ __forceinline__ void split2(float x, float y, __nv_bfloat162& hi, __nv_bfloat162& lo) {
    hi.x = __float2bfloat16(x); hi.y = __float2bfloat16(y);
    lo.x = __float2bfloat16(x - __bfloat162float(hi.x));
    lo.y = __float2bfloat16(y - __bfloat162float(hi.y));
}

// smem tile layout (per stage): A_hi(10240) A_lo(10240) B_hi(10240) B_lo(10240)
// rows stored with 80-byte stride (40 halves): bank stride 20 -> conflict-free ldmatrix
#define WSTAGE 40960
#define WSMEM  (2 * WSTAGE)

// C[m,n] = sum_k A[m,k]*B[n,k].  A: M x lda fp32 (K zero-padded, guard-free).
// B: Nreal x ldb fp32 (guarded).  EPI: 0 = row-major store (ldc), 1 = (b,n,l) store.
// BV: B gmem vector width (2 or 4).
template<int EPI, int BV>
__global__ __launch_bounds__(256, 1) void wgemm(
    const float* __restrict__ A, const float* __restrict__ B, float* __restrict__ C,
    int Nreal, int Kreal, int lda, int ldb, int ldc, int nch)
{
    extern __shared__ char smem[];
    const int tid = threadIdx.x;
    const int wid = tid >> 5;
    const int lane = tid & 31;
    const int wm = wid >> 2;          // 0-1
    const int wn = wid & 3;           // 0-3
    const int row0 = blockIdx.y * 128;
    const int col0 = blockIdx.x * 128;
    const uint32_t sb = smem_u32(smem);

    // ldmatrix per-lane address components
    const int aRow = wm * 64 + (lane & 7) + ((lane >> 3) & 1) * 8;   // + mt*16
    const int aK   = ((lane >> 4) & 1) * 8;                          // + kk
    const uint32_t aoff = (uint32_t)(aRow * 80 + aK * 2);
    const int bRow = wn * 32 + (lane & 7) + ((lane >> 4) & 1) * 8;   // + ntp*16
    const int bK   = ((lane >> 3) & 1) * 8;
    const uint32_t boff = (uint32_t)(bRow * 80 + bK * 2);

    float acc[4][4][4];
#pragma unroll
    for (int i = 0; i < 4; i++)
#pragma unroll
        for (int j = 0; j < 4; j++)
#pragma unroll
            for (int q = 0; q < 4; q++) acc[i][j][q] = 0.f;

    // gmem-load register staging
    float4 rA[4];
    float2 rB2[16];
    float4 rB4[8];

    // ---- loaders ----
    auto loadA = [&](int c) {
        const float* Ab = A + (size_t)row0 * lda + c * 32;
#pragma unroll
        for (int it = 0; it < 4; it++) {
            int idx = tid + it * 256;
            rA[it] = *(const float4*)(Ab + (size_t)(idx >> 3) * lda + (idx & 7) * 4);
        }
    };
    auto loadB = [&](int c) {
        const int k0 = c * 32;
        if (BV == 2) {
#pragma unroll
            for (int it = 0; it < 8; it++) {
                int idx = tid + it * 256;
                int gn = col0 + (idx >> 4), gk = k0 + (idx & 15) * 2;
                float2 v = make_float2(0.f, 0.f);
                if (gn < Nreal) {
                    const float* bp = B + (size_t)gn * ldb + gk;
                    if (gk + 1 < Kreal) v = *(const float2*)bp;
                    else if (gk < Kreal) v.x = *bp;
                }
                rB2[it] = v;
            }
        } else {
#pragma unroll
            for (int it = 0; it < 4; it++) {
                int idx = tid + it * 256;
                int gn = col0 + (idx >> 3), gk = k0 + (idx & 7) * 4;
                float4 v = make_float4(0.f, 0.f, 0.f, 0.f);
                if (gn < Nreal) {
                    const float* bp = B + (size_t)gn * ldb + gk;
                    if (gk + 3 < Kreal) v = *(const float4*)bp;
                    else {
                        if (gk     < Kreal) v.x = bp[0];
                        if (gk + 1 < Kreal) v.y = bp[1];
                        if (gk + 2 < Kreal) v.z = bp[2];
                    }
                }
                rB4[it] = v;
            }
        }
    };
    auto storeStage = [&](int s) {
        char* st = smem + s * WSTAGE;
#pragma unroll
        for (int it = 0; it < 4; it++) {
            int idx = tid + it * 256;
            uint32_t o = (uint32_t)((idx >> 3) * 80 + (idx & 7) * 8);
            __nv_bfloat162 h0, l0, h1, l1;
            split2(rA[it].x, rA[it].y, h0, l0);
            split2(rA[it].z, rA[it].w, h1, l1);
            *(__nv_bfloat162*)(st + o)             = h0;
            *(__nv_bfloat162*)(st + o + 4)         = h1;
            *(__nv_bfloat162*)(st + 10240 + o)     = l0;
            *(__nv_bfloat162*)(st + 10240 + o + 4) = l1;
        }
        if (BV == 2) {
#pragma unroll
            for (int it = 0; it < 8; it++) {
                int idx = tid + it * 256;
                uint32_t o = (uint32_t)((idx >> 4) * 80 + (idx & 15) * 4);
                __nv_bfloat162 h, l;
                split2(rB2[it].x, rB2[it].y, h, l);
                *(__nv_bfloat162*)(st + 20480 + o) = h;
                *(__nv_bfloat162*)(st + 30720 + o) = l;
            }
        } else {
#pragma unroll
            for (int it = 0; it < 4; it++) {
                int idx = tid + it * 256;
                uint32_t o = (uint32_t)((idx >> 3) * 80 + (idx & 7) * 8);
                __nv_bfloat162 h0, l0, h1, l1;
                split2(rB4[it].x, rB4[it].y, h0, l0);
                split2(rB4[it].z, rB4[it].w, h1, l1);
                *(__nv_bfloat162*)(st + 20480 + o)     = h0;
                *(__nv_bfloat162*)(st + 20480 + o + 4) = h1;
                *(__nv_bfloat162*)(st + 30720 + o)     = l0;
                *(__nv_bfloat162*)(st + 30720 + o + 4) = l1;
            }
        }
    };

    // ---- prologue ----
    loadA(0); loadB(0); storeStage(0);
    __syncthreads();

    for (int c = 0; c < nch; c++) {
        const int cur = c & 1;
        if (c + 1 < nch) { loadA(c + 1); loadB(c + 1); }

        const uint32_t stA_hi = sb + cur * WSTAGE;
        const uint32_t stA_lo = stA_hi + 10240;
        const uint32_t stB_hi = stA_hi + 20480;
        const uint32_t stB_lo = stA_hi + 30720;

#pragma unroll
        for (int kk2 = 0; kk2 < 2; kk2++) {
            const uint32_t kb = kk2 * 32;   // kk*2 bytes (kk = 16*kk2)
            uint32_t afh[4][4], afl[4][4], bfh[4][2], bfl[4][2];
#pragma unroll
            for (int mt = 0; mt < 4; mt++) {
                uint32_t ad = aoff + mt * 1280 + kb;
                ldsm4(afh[mt][0], afh[mt][1], afh[mt][2], afh[mt][3], stA_hi + ad);
                ldsm4(afl[mt][0], afl[mt][1], afl[mt][2], afl[mt][3], stA_lo + ad);
            }
#pragma unroll
            for (int ntp = 0; ntp < 2; ntp++) {
                uint32_t bd = boff + ntp * 1280 + kb;
                ldsm4(bfh[ntp*2][0], bfh[ntp*2][1], bfh[ntp*2+1][0], bfh[ntp*2+1][1], stB_hi + bd);
                ldsm4(bfl[ntp*2][0], bfl[ntp*2][1], bfl[ntp*2+1][0], bfl[ntp*2+1][1], stB_lo + bd);
            }
#pragma unroll
            for (int mt = 0; mt < 4; mt++)
#pragma unroll
                for (int nt = 0; nt < 4; nt++) {
                    mma_bf16(acc[mt][nt], afh[mt], bfh[nt]);
                    mma_bf16(acc[mt][nt], afh[mt], bfl[nt]);
                    mma_bf16(acc[mt][nt], afl[mt], bfh[nt]);
                }
        }
        if (c + 1 < nch) storeStage(1 - cur);
        __syncthreads();
    }

    // ---- epilogue ----
    const int g = lane >> 2;
    const int tq = lane & 3;
#pragma unroll
    for (int mt = 0; mt < 4; mt++) {
        const int m = row0 + wm * 64 + mt * 16 + g;
#pragma unroll
        for (int nt = 0; nt < 4; nt++) {
            const int n = col0 + wn * 32 + nt * 8 + tq * 2;
            if (n >= Nreal) continue;
            if (EPI == 0) {
                *(float2*)&C[(size_t)m * ldc + n] =
                    make_float2(acc[mt][nt][0], acc[mt][nt][1]);
                *(float2*)&C[(size_t)(m + 8) * ldc + n] =
                    make_float2(acc[mt][nt][2], acc[mt][nt][3]);
            } else {
                size_t ob = ((size_t)(m >> 8) * DMODEL + n) * 256 + (m & 255);
                C[ob]           = acc[mt][nt][0];
                C[ob + 256]     = acc[mt][nt][1];
                C[ob + 8]       = acc[mt][nt][2];
                C[ob + 256 + 8] = acc[mt][nt][3];
            }
        }
    }
}

// ================= SIMT pieces =================
__global__ void k_bnprep(const float* __restrict__ gamma, const float* __restrict__ beta,
                         const float* __restrict__ mean, const float* __restrict__ var) {
    int i = threadIdx.x;
    if (i < 512) {
        float inv = rsqrtf(var[i] + 1e-5f) * gamma[i];
        g_bn[i] = inv;
        g_bn[512 + i] = beta[i] - mean[i] * inv;
    }
}

__device__ __forceinline__ float xx_val(int i) { return -0.3f + (0.6f / 15.0f) * (float)i; }

__global__ void k_build(const float* __restrict__ x, const float* __restrict__ pc) {
    __shared__ float tile[32][33];
    int b = blockIdx.x;
    int c0 = blockIdx.y * 32;
    int l0 = blockIdx.z * 32;
    int tx = threadIdx.x, ty = threadIdx.y;
    int c = c0 + ty, l = l0 + tx;
    if (c < COMBC) {
        float v;
        if (c < 512)       v = x[((size_t)(b * 512 + c)) * 256 + l];
        else if (c == 512) v = xx_val(l & 15);
        else if (c == 513) v = xx_val(l >> 4);
        else               v = pc[b * 256 + (c - 514)];
        tile[ty][tx] = v;
    }
    __syncthreads();
    c = c0 + tx; l = l0 + ty;
    if (c < COMBC)
        g_seq[((size_t)(b * 256 + l)) * LDSEQ + c] = tile[tx][ty];
}

// SIMT SGEMM for small GEMMs. EP: 1 BN+ReLU6, 2 bias+softplus, 4 remap cols
template<int EP>
__global__ __launch_bounds__(256, 2) void sgemm(
    const float* __restrict__ A, const float* __restrict__ B, float* __restrict__ C,
    int M, int N, int K, int lda, int ldb, int ldc,
    const float* __restrict__ aux1, const float* __restrict__ aux2)
{
    __shared__ float As[8][128];
    __shared__ float Bs[8][128];
    const int tid = threadIdx.x;
    const int tx = tid & 15, ty = tid >> 4;
    const int row0 = blockIdx.y * 128, col0 = blockIdx.x * 128;
    const int lm = tid >> 1;
    const int lk = (tid & 1) * 4;
    float acc[8][8];
#pragma unroll
    for (int i = 0; i < 8; i++)
#pragma unroll
        for (int j = 0; j < 8; j++) acc[i][j] = 0.f;

    const int gmA = row0 + lm;
    const int gnB = col0 + lm;
    for (int k0 = 0; k0 < K; k0 += 8) {
#pragma unroll
        for (int j = 0; j < 4; j++) {
            int gk = k0 + lk + j;
            As[lk + j][lm] = (gmA < M && gk < K) ? A[(size_t)gmA * lda + gk] : 0.f;
            Bs[lk + j][lm] = (gnB < N && gk < K) ? B[(size_t)gnB * ldb + gk] : 0.f;
        }
        __syncthreads();
#pragma unroll
        for (int kk = 0; kk < 8; kk++) {
            float a[8], bb[8];
#pragma unroll
            for (int i = 0; i < 8; i++) a[i] = As[kk][ty * 8 + i];
#pragma unroll
            for (int j = 0; j < 8; j++) bb[j] = Bs[kk][tx * 8 + j];
#pragma unroll
            for (int i = 0; i < 8; i++)
#pragma unroll
                for (int j = 0; j < 8; j++) acc[i][j] = fmaf(a[i], bb[j], acc[i][j]);
        }
        __syncthreads();
    }
#pragma unroll
    for (int i = 0; i < 8; i++) {
        int gm = row0 + ty * 8 + i;
        if (gm >= M) continue;
#pragma unroll
        for (int j = 0; j < 8; j++) {
            int gn = col0 + tx * 8 + j;
            if (gn >= N) continue;
            float v = acc[i][j];
            if (EP == 1) {
                v = v * aux1[gn] + aux2[gn];
                v = fminf(fmaxf(v, 0.f), 6.f);
                C[(size_t)gm * ldc + gn] = v;
            } else if (EP == 2) {
                v += aux1[gn];
                v = (v > 20.f) ? v : log1pf(__expf(v));
                C[(size_t)gm * ldc + gn] = v;
            } else {
                int cc = (gn < 81) ? gn : gn + 3;
                C[(size_t)gm * DBL_LD + cc] = v;
            }
        }
    }
}

__global__ void k_reduce0() {
    int b = blockIdx.x, d = threadIdx.x;
    float acc = 0.f;
    for (int l = 0; l < 256; l++)
        acc += g_tmp0[((size_t)(b * 256 + l)) * 128 + d];
    g_y0[b * 128 + d] = acc * (1.f / 256.f);
}

__global__ void k_pool() {
    int b = blockIdx.x;
    int spg = blockIdx.y;
    int s, row_base, local;
    if (spg < 25)       { s = 5;  row_base = 0;    local = spg; }
    else if (spg < 106) { s = 9;  row_base = 1600; local = spg - 25; }
    else                { s = 13; row_base = 6784; local = spg - 106; }
    int o = local / s, p = local % s;
    int h0 = (o * 16) / s, h1 = ((o + 1) * 16 + s - 1) / s;
    int w0 = (p * 16) / s, w1 = ((p + 1) * 16 + s - 1) / s;
    float wgt = 1.f / (float)((h1 - h0) * (w1 - w0));
    size_t orow = (size_t)(row_base + b * s * s + local) * COMBC;
    for (int c = threadIdx.x; c < COMBC; c += 256) {
        float acc = 0.f;
        for (int h = h0; h < h1; h++)
            for (int w = w0; w < w1; w++)
                acc += g_seq[((size_t)(b * 256 + h * 16 + w)) * LDSEQ + c];
        g_pooled[orow + c] = acc * wgt;
    }
}

__global__ void k_assemble() {
    int m = blockIdx.x;
    int b = m >> 8, l = m & 255;
    int o = l >> 4, p = l & 15;
    int t = threadIdx.x;
    if (t < 30) g_seq[(size_t)m * LDSEQ + 1282 + t] = 0.f;  // zero K-pad
    if (t < 128) {
        g_seq[(size_t)m * LDSEQ + 770 + t] = g_y0[b * 128 + t];
    } else {
        int i = (t - 128) >> 7;
        int d = (t - 128) & 127;
        int s      = (i == 0) ? 5 : (i == 1) ? 9 : 13;
        int base_r = (i == 0) ? 0 : (i == 1) ? 1600 : 6784;
        float fs = (float)s;
        float so = (o + 0.5f) * fs / 16.0f - 0.5f;
        so = fminf(fmaxf(so, 0.f), fs - 1.0f);
        int h0 = (int)floorf(so); int h1 = min(h0 + 1, s - 1); float fo = so - (float)h0;
        float sp = (p + 0.5f) * fs / 16.0f - 0.5f;
        sp = fminf(fmaxf(sp, 0.f), fs - 1.0f);
        int w0 = (int)floorf(sp); int w1 = min(w0 + 1, s - 1); float fp = sp - (float)w0;
        const float* yb = g_yp + (size_t)(base_r + b * s * s) * 128 + d;
        float v00 = yb[(size_t)(h0 * s + w0) * 128];
        float v01 = yb[(size_t)(h0 * s + w1) * 128];
        float v10 = yb[(size_t)(h1 * s + w0) * 128];
        float v11 = yb[(size_t)(h1 * s + w1) * 128];
        float v = (1.f - fo) * ((1.f - fp) * v00 + fp * v01)
                + fo * ((1.f - fp) * v10 + fp * v11);
        g_seq[(size_t)m * LDSEQ + 898 + i * 128 + d] = v;
    }
}

__global__ void k_conv1d(const float* __restrict__ w, const float* __restrict__ bias) {
    int m = blockIdx.x;
    int d = blockIdx.y * 256 + threadIdx.x;
    if (d >= DINNER) return;
    int l = m & 255;
    size_t base = (size_t)m * (2 * DINNER) + d;
    float acc = bias[d];
    const float* wd = w + d * 4;
#pragma unroll
    for (int j = 0; j < 4; j++) {
        int l2 = l - 3 + j;
        if (l2 >= 0) acc += wd[j] * g_xz[base + (size_t)(j - 3) * (2 * DINNER)];
    }
    g_u[(size_t)m * DINNER + d] = acc / (1.f + __expf(-acc));
}

__global__ __launch_bounds__(256) void k_scan(const float* __restrict__ A_log,
                                              const float* __restrict__ Dp) {
    int b = blockIdx.y;
    int d = blockIdx.x * 256 + threadIdx.x;
    if (d >= DINNER) {
        if (d < LDYS) {   // zero K-pad columns of g_ys
            float* yo = g_ys + (size_t)b * 256 * LDYS + d;
            for (int l = 0; l < 256; l++) yo[(size_t)l * LDYS] = 0.f;
        }
        return;
    }
    float A[DSTATE];
#pragma unroll
    for (int n = 0; n < DSTATE; n++) A[n] = -__expf(A_log[d * DSTATE + n]);
    float Dd = Dp[d];
    float h[DSTATE];
#pragma unroll
    for (int n = 0; n < DSTATE; n++) h[n] = 0.f;

    const float* dtp = g_dtv + (size_t)b * 256 * DINNER + d;
    const float* up  = g_u   + (size_t)b * 256 * DINNER + d;
    const float* zp  = g_xz  + (size_t)b * 256 * (2 * DINNER) + DINNER + d;
    const float* bc  = g_dbl + (size_t)b * 256 * DBL_LD;
    float* yo        = g_ys  + (size_t)b * 256 * LDYS + d;

    for (int l = 0; l < 256; l++) {
        float dt = dtp[(size_t)l * DINNER];
        float u  = up [(size_t)l * DINNER];
        const float4* bcrow = reinterpret_cast<const float4*>(bc + (size_t)l * DBL_LD + 84);
        float4 Bv0 = bcrow[0], Bv1 = bcrow[1], Bv2 = bcrow[2], Bv3 = bcrow[3];
        float4 Cv0 = bcrow[4], Cv1 = bcrow[5], Cv2 = bcrow[6], Cv3 = bcrow[7];
        float Bm[16] = {Bv0.x,Bv0.y,Bv0.z,Bv0.w, Bv1.x,Bv1.y,Bv1.z,Bv1.w,
                        Bv2.x,Bv2.y,Bv2.z,Bv2.w, Bv3.x,Bv3.y,Bv3.z,Bv3.w};
        float Cm[16] = {Cv0.x,Cv0.y,Cv0.z,Cv0.w, Cv1.x,Cv1.y,Cv1.z,Cv1.w,
                        Cv2.x,Cv2.y,Cv2.z,Cv2.w, Cv3.x,Cv3.y,Cv3.z,Cv3.w};
        float xbu = dt * u;
        float y = 0.f;
#pragma unroll
        for (int n = 0; n < DSTATE; n++) {
            float dA = __expf(dt * A[n]);
            h[n] = dA * h[n] + xbu * Bm[n];
            y += h[n] * Cm[n];
        }
        float z = zp[(size_t)l * (2 * DINNER)];
        float sil = z / (1.f + __expf(-z));
        yo[(size_t)l * LDYS] = (y + u * Dd) * sil;
    }
}

// ================= launch =================
extern "C" void kernel_launch(void* const* d_in, const int* in_sizes, int n_in,
                              void* d_out, int out_size) {
    (void)in_sizes; (void)n_in; (void)out_size;
    const float* x         = (const float*)d_in[0];
    const float* pc_emb    = (const float*)d_in[1];
    const float* conv_w    = (const float*)d_in[2];
    const float* bn_gamma  = (const float*)d_in[3];
    const float* bn_beta   = (const float*)d_in[4];
    const float* bn_mean   = (const float*)d_in[5];
    const float* bn_var    = (const float*)d_in[6];
    const float* in_proj_w = (const float*)d_in[7];
    const float* conv1d_w  = (const float*)d_in[8];
    const float* conv1d_b  = (const float*)d_in[9];
    const float* x_proj_w  = (const float*)d_in[10];
    const float* dt_proj_w = (const float*)d_in[11];
    const float* dt_proj_b = (const float*)d_in[12];
    const float* A_log     = (const float*)d_in[13];
    const float* Dvec      = (const float*)d_in[14];
    const float* out_proj_w= (const float*)d_in[15];
    float* out = (float*)d_out;

    float *p_seq, *p_tmp0, *p_pooled, *p_yp, *p_xz, *p_u, *p_dbl, *p_dtv, *p_ys, *p_bn;
    cudaGetSymbolAddress((void**)&p_seq,    g_seq);
    cudaGetSymbolAddress((void**)&p_tmp0,   g_tmp0);
    cudaGetSymbolAddress((void**)&p_pooled, g_pooled);
    cudaGetSymbolAddress((void**)&p_yp,     g_yp);
    cudaGetSymbolAddress((void**)&p_xz,     g_xz);
    cudaGetSymbolAddress((void**)&p_u,      g_u);
    cudaGetSymbolAddress((void**)&p_dbl,    g_dbl);
    cudaGetSymbolAddress((void**)&p_dtv,    g_dtv);
    cudaGetSymbolAddress((void**)&p_ys,     g_ys);
    cudaGetSymbolAddress((void**)&p_bn,     g_bn);

    cudaFuncSetAttribute(wgemm<0,2>, cudaFuncAttributeMaxDynamicSharedMemorySize, WSMEM);
    cudaFuncSetAttribute(wgemm<1,4>, cudaFuncAttributeMaxDynamicSharedMemorySize, WSMEM);

    // PPM
    k_bnprep<<<1, 512>>>(bn_gamma, bn_beta, bn_mean, bn_var);
    k_build<<<dim3(64, 25, 8), dim3(32, 32)>>>(x, pc_emb);
    sgemm<1><<<dim3(1, 128), 256>>>(p_seq, conv_w, p_tmp0,
                                    MSEQ, 128, COMBC, LDSEQ, COMBC, 128, p_bn, p_bn + 512);
    k_reduce0<<<64, 128>>>();
    k_pool<<<dim3(64, 275), 256>>>();
    sgemm<1><<<dim3(1, 13), 256>>>(p_pooled, conv_w + 1 * 128 * COMBC, p_yp,
                                   1600, 128, COMBC, COMBC, COMBC, 128,
                                   p_bn + 128, p_bn + 512 + 128);
    sgemm<1><<<dim3(1, 41), 256>>>(p_pooled + (size_t)1600 * COMBC, conv_w + 2 * 128 * COMBC,
                                   p_yp + (size_t)1600 * 128,
                                   5184, 128, COMBC, COMBC, COMBC, 128,
                                   p_bn + 256, p_bn + 512 + 256);
    sgemm<1><<<dim3(1, 85), 256>>>(p_pooled + (size_t)6784 * COMBC, conv_w + 3 * 128 * COMBC,
                                   p_yp + (size_t)6784 * 128,
                                   10816, 128, COMBC, COMBC, COMBC, 128,
                                   p_bn + 384, p_bn + 512 + 384);
    k_assemble<<<MSEQ, 512>>>();

    // Mamba
    // in_proj: M=16384, N=5128, K=1282 (padded 1312 -> 41 chunks), bf16-split mma.sync
    wgemm<0,2><<<dim3(41, 128), 256, WSMEM>>>(p_seq, in_proj_w, p_xz,
                                              2 * DINNER, DMODEL, LDSEQ, DMODEL,
                                              2 * DINNER, 41);
    k_conv1d<<<dim3(MSEQ, 11), 256>>>(conv1d_w, conv1d_b);
    sgemm<4><<<dim3(1, 128), 256>>>(p_u, x_proj_w, p_dbl,
                                    MSEQ, 113, DINNER, DINNER, DINNER, DBL_LD,
                                    nullptr, nullptr);
    sgemm<2><<<dim3(21, 128), 256>>>(p_dbl, dt_proj_w, p_dtv,
                                     MSEQ, DINNER, 81, DBL_LD, 81, DINNER,
                                     dt_proj_b, nullptr);
    k_scan<<<dim3(11, 64), 256>>>(A_log, Dvec);
    // out_proj: M=16384, N=1282, K=2564 (padded 2592 -> 81 chunks), (b,n,l) store
    wgemm<1,4><<<dim3(11, 128), 256, WSMEM>>>(p_ys, out_proj_w, out,
                                              DMODEL, DINNER, LDYS, DINNER, 0, 81);
}

// round 11
// speedup vs baseline: 2.7948x; 1.4073x over previous
#include <cuda_runtime.h>
#include <cuda_bf16.h>
#include <math.h>
#include <stdint.h>

#define BB 64
#define COMBC 770
#define DMODEL 1282
#define DINNER 2564
#define DSTATE 16
#define MSEQ 16384
#define LDSEQ 1312      // padded d_model (41*32)
#define DBL_LD 116

// ---------------- scratch (device globals; no allocations allowed) ----------------
__device__ __align__(128) float g_seq[(size_t)MSEQ * LDSEQ];     // padded, pad cols zeroed
__device__ __align__(128) float g_tmp0[(size_t)MSEQ * 128];
__device__ __align__(128) float g_y0[BB * 128];
__device__ __align__(128) float g_pooled[(size_t)17600 * COMBC];
__device__ __align__(128) float g_yp[(size_t)17600 * 128];
__device__ __align__(128) float g_xz[(size_t)MSEQ * 2 * DINNER];
__device__ __align__(128) float g_u[(size_t)MSEQ * DINNER];
__device__ __align__(128) float g_dbl[(size_t)MSEQ * DBL_LD];
__device__ __align__(128) float g_dtv[(size_t)MSEQ * DINNER];
__device__ __align__(128) float g_bn[1024];

// hi/lo bf16 chunk-interleaved operands: [(m*nch + c)*64 + j], j<32 hi(k=c*32+j), j>=32 lo
__device__ __align__(128) __nv_bfloat16 g_seqhl [(size_t)MSEQ * 41 * 64];
__device__ __align__(128) __nv_bfloat16 g_winhl [(size_t)5248 * 41 * 64];
__device__ __align__(128) __nv_bfloat16 g_uhl   [(size_t)MSEQ * 81 * 64];
__device__ __align__(128) __nv_bfloat16 g_xwhl  [(size_t)128  * 81 * 64];
__device__ __align__(128) __nv_bfloat16 g_dblhl [(size_t)MSEQ * 3  * 64];
__device__ __align__(128) __nv_bfloat16 g_dtwhl [(size_t)2688 * 3  * 64];
__device__ __align__(128) __nv_bfloat16 g_yshl  [(size_t)MSEQ * 81 * 64];
__device__ __align__(128) __nv_bfloat16 g_wouthl[(size_t)1408 * 81 * 64];

// ================= helpers =================
__device__ __forceinline__ uint32_t smem_u32(const void* p) {
    uint32_t a;
    asm("{ .reg .u64 t; cvta.to.shared.u64 t, %1; cvt.u32.u64 %0, t; }" : "=r"(a) : "l"(p));
    return a;
}
__device__ __forceinline__ void ldsm4(uint32_t& r0, uint32_t& r1, uint32_t& r2, uint32_t& r3,
                                      uint32_t addr) {
    asm volatile("ldmatrix.sync.aligned.m8n8.x4.shared.b16 {%0,%1,%2,%3}, [%4];"
                 : "=r"(r0), "=r"(r1), "=r"(r2), "=r"(r3) : "r"(addr));
}
__device__ __forceinline__ void mma_bf16(float* d, const uint32_t* a, const uint32_t* b) {
    asm volatile(
        "mma.sync.aligned.m16n8k16.row.col.f32.bf16.bf16.f32 "
        "{%0,%1,%2,%3}, {%4,%5,%6,%7}, {%8,%9}, {%0,%1,%2,%3};"
        : "+f"(d[0]), "+f"(d[1]), "+f"(d[2]), "+f"(d[3])
        : "r"(a[0]), "r"(a[1]), "r"(a[2]), "r"(a[3]), "r"(b[0]), "r"(b[1]));
}
__device__ __forceinline__ void split2(float x, float y, __nv_bfloat162& hi, __nv_bfloat162& lo) {
    hi.x = __float2bfloat16(x); hi.y = __float2bfloat16(y);
    lo.x = __float2bfloat16(x - __bfloat162float(hi.x));
    lo.y = __float2bfloat16(y - __bfloat162float(hi.y));
}
__device__ __forceinline__ void cpasync16(uint32_t s, const void* g) {
    asm volatile("cp.async.cg.shared.global [%0], [%1], 16;" :: "r"(s), "l"(g));
}
#define CP_COMMIT() asm volatile("cp.async.commit_group;" ::: "memory")
#define CP_WAIT1()  asm volatile("cp.async.wait_group 1;" ::: "memory")

// ---------------- generic fp32 -> hi/lo chunked convert ----------------
__global__ void k_cvt(const float* __restrict__ src, __nv_bfloat16* __restrict__ dst,
                      int Mreal, int Kreal, int lds, int nch, int total) {
    int i = blockIdx.x * 256 + threadIdx.x;
    if (i >= total) return;
    int jp = i & 15;
    int t = i >> 4;
    int c = t % nch;
    int m = t / nch;
    int k = c * 32 + jp * 2;
    float f0 = 0.f, f1 = 0.f;
    if (m < Mreal) {
        if (k < Kreal)     f0 = src[(size_t)m * lds + k];
        if (k + 1 < Kreal) f1 = src[(size_t)m * lds + k + 1];
    }
    __nv_bfloat162 hi, lo;
    split2(f0, f1, hi, lo);
    size_t base = ((size_t)(m * nch + c)) * 64 + jp * 2;
    *(__nv_bfloat162*)&dst[base]      = hi;
    *(__nv_bfloat162*)&dst[base + 32] = lo;
}

// ===== wgemm2: cp.async-pipelined bf16-split GEMM on pre-converted hi/lo operands =====
// C[m,n] = sum_k A[m,k]*B[n,k]. 128x128 tile, 3 stages x 32KB.
// EPI: 0 plain(ldc), 1 (b,n,l) store, 2 x_proj (remap fp32 + dbl_hl), 3 bias+softplus
#define WS2 98304

template<int EPI>
__global__ __launch_bounds__(256, 2) void wgemm2(
    const __nv_bfloat16* __restrict__ Ahl, const __nv_bfloat16* __restrict__ Bhl,
    float* __restrict__ C, int Nreal, int ldc, int nch, const float* __restrict__ aux)
{
    extern __shared__ char smem[];
    const int tid = threadIdx.x;
    const int wid = tid >> 5;
    const int lane = tid & 31;
    const int wm = wid >> 2, wn = wid & 3;
    const int row0 = blockIdx.y * 128;
    const int col0 = blockIdx.x * 128;
    const uint32_t sb = smem_u32(smem);

    // cp.async per-thread mapping (4 x 16B per operand per stage)
    const int cp_r0 = tid >> 3, cp_c8 = tid & 7;
    const uint32_t cp_sw = (uint32_t)((cp_c8 ^ (cp_r0 & 7)) << 4);

    auto issue = [&](int c, int s) {
        const uint32_t st = sb + s * 32768;
        const size_t ga = ((size_t)(row0 + cp_r0) * nch + c) * 64 + cp_c8 * 8;
        const size_t gb = ((size_t)(col0 + cp_r0) * nch + c) * 64 + cp_c8 * 8;
#pragma unroll
        for (int q = 0; q < 4; q++) {
            uint32_t so = (uint32_t)((cp_r0 + q * 32) * 128) + cp_sw;
            cpasync16(st + so,         Ahl + ga + (size_t)q * 32 * nch * 64);
            cpasync16(st + 16384 + so, Bhl + gb + (size_t)q * 32 * nch * 64);
        }
    };

    // fragment addressing
    const int r3 = lane & 7;
    const uint32_t aRowB = (uint32_t)((wm * 64 + r3 + ((lane >> 3) & 1) * 8) * 128);
    const int aSel = (lane >> 4) & 1;
    const uint32_t bRowB = (uint32_t)(16384 + (wn * 32 + r3 + ((lane >> 4) & 1) * 8) * 128);
    const int bSel = (lane >> 3) & 1;

    float acc[4][4][4];
#pragma unroll
    for (int i = 0; i < 4; i++)
#pragma unroll
        for (int j = 0; j < 4; j++)
#pragma unroll
            for (int q = 0; q < 4; q++) acc[i][j][q] = 0.f;

    issue(0, 0); CP_COMMIT();
    if (nch > 1) issue(1, 1);
    CP_COMMIT();

    for (int c = 0; c < nch; c++) {
        const int s = c % 3;
        CP_WAIT1();
        __syncthreads();
        if (c + 2 < nch) issue(c + 2, (c + 2) % 3);
        CP_COMMIT();
        const uint32_t st = sb + s * 32768;
#pragma unroll
        for (int kk2 = 0; kk2 < 2; kk2++) {
            const int aCh = aSel + kk2 * 2;
            const uint32_t aHi = (uint32_t)((aCh ^ r3) << 4);
            const uint32_t aLo = (uint32_t)(((aCh + 4) ^ r3) << 4);
            const int bCh = bSel + kk2 * 2;
            const uint32_t bHi = (uint32_t)((bCh ^ r3) << 4);
            const uint32_t bLo = (uint32_t)(((bCh + 4) ^ r3) << 4);
            uint32_t bfh[4][2], bfl[4][2];
#pragma unroll
            for (int ntp = 0; ntp < 2; ntp++) {
                uint32_t ba = st + bRowB + ntp * 2048;
                ldsm4(bfh[ntp*2][0], bfh[ntp*2][1], bfh[ntp*2+1][0], bfh[ntp*2+1][1], ba + bHi);
                ldsm4(bfl[ntp*2][0], bfl[ntp*2][1], bfl[ntp*2+1][0], bfl[ntp*2+1][1], ba + bLo);
            }
#pragma unroll
            for (int mt = 0; mt < 4; mt++) {
                uint32_t aa = st + aRowB + mt * 2048;
                uint32_t afh[4], afl[4];
                ldsm4(afh[0], afh[1], afh[2], afh[3], aa + aHi);
                ldsm4(afl[0], afl[1], afl[2], afl[3], aa + aLo);
#pragma unroll
                for (int nt = 0; nt < 4; nt++) {
                    mma_bf16(acc[mt][nt], afh, bfh[nt]);
                    mma_bf16(acc[mt][nt], afh, bfl[nt]);
                    mma_bf16(acc[mt][nt], afl, bfh[nt]);
                }
            }
        }
    }

    // ---- epilogue ----
    const int g = lane >> 2, tq = lane & 3;
#pragma unroll
    for (int mt = 0; mt < 4; mt++) {
        const int m = row0 + wm * 64 + mt * 16 + g;
#pragma unroll
        for (int nt = 0; nt < 4; nt++) {
            const int n = col0 + wn * 32 + nt * 8 + tq * 2;
            float* a4 = acc[mt][nt];
            if (EPI == 0) {
                if (n < Nreal) {
                    *(float2*)&C[(size_t)m * ldc + n] = make_float2(a4[0], a4[1]);
                    *(float2*)&C[(size_t)(m + 8) * ldc + n] = make_float2(a4[2], a4[3]);
                }
            } else if (EPI == 1) {
                if (n < Nreal) {
                    size_t ob = ((size_t)(m >> 8) * DMODEL + n) * 256 + (m & 255);
                    C[ob] = a4[0]; C[ob + 256] = a4[1];
                    C[ob + 8] = a4[2]; C[ob + 256 + 8] = a4[3];
                }
            } else if (EPI == 2) {
#pragma unroll
                for (int e = 0; e < 4; e++) {
                    int nn = n + (e & 1), mm = m + (e >> 1) * 8;
                    float v = a4[e];
                    if (nn < 81)       C[(size_t)mm * DBL_LD + nn] = v;
                    else if (nn < 113) C[(size_t)mm * DBL_LD + nn + 3] = v;
                    if (nn < 96) {
                        float vv = (nn < 81) ? v : 0.f;
                        __nv_bfloat16 hi = __float2bfloat16(vv);
                        __nv_bfloat16 lo = __float2bfloat16(vv - __bfloat162float(hi));
                        size_t hb = ((size_t)mm * 3 + (nn >> 5)) * 64 + (nn & 31);
                        g_dblhl[hb] = hi; g_dblhl[hb + 32] = lo;
                    }
                }
            } else {
#pragma unroll
                for (int e = 0; e < 4; e++) {
                    int nn = n + (e & 1), mm = m + (e >> 1) * 8;
                    if (nn < Nreal) {
                        float v = a4[e] + aux[nn];
                        v = (v > 20.f) ? v : log1pf(__expf(v));
                        C[(size_t)mm * DINNER + nn] = v;
                    }
                }
            }
        }
    }
}

// ================= SIMT pieces =================
__global__ void k_bnprep(const float* __restrict__ gamma, const float* __restrict__ beta,
                         const float* __restrict__ mean, const float* __restrict__ var) {
    int i = threadIdx.x;
    if (i < 512) {
        float inv = rsqrtf(var[i] + 1e-5f) * gamma[i];
        g_bn[i] = inv;
        g_bn[512 + i] = beta[i] - mean[i] * inv;
    }
}

__device__ __forceinline__ float xx_val(int i) { return -0.3f + (0.6f / 15.0f) * (float)i; }

__global__ void k_build(const float* __restrict__ x, const float* __restrict__ pc) {
    __shared__ float tile[32][33];
    int b = blockIdx.x;
    int c0 = blockIdx.y * 32;
    int l0 = blockIdx.z * 32;
    int tx = threadIdx.x, ty = threadIdx.y;
    int c = c0 + ty, l = l0 + tx;
    if (c < COMBC) {
        float v;
        if (c < 512)       v = x[((size_t)(b * 512 + c)) * 256 + l];
        else if (c == 512) v = xx_val(l & 15);
        else if (c == 513) v = xx_val(l >> 4);
        else               v = pc[b * 256 + (c - 514)];
        tile[ty][tx] = v;
    }
    __syncthreads();
    c = c0 + tx; l = l0 + ty;
    if (c < COMBC)
        g_seq[((size_t)(b * 256 + l)) * LDSEQ + c] = tile[tx][ty];
}

// SIMT SGEMM (PPM convs only). EP=1: BN+ReLU6
template<int EP>
__global__ __launch_bounds__(256, 2) void sgemm(
    const float* __restrict__ A, const float* __restrict__ B, float* __restrict__ C,
    int M, int N, int K, int lda, int ldb, int ldc,
    const float* __restrict__ aux1, const float* __restrict__ aux2)
{
    __shared__ float As[8][128];
    __shared__ float Bs[8][128];
    const int tid = threadIdx.x;
    const int tx = tid & 15, ty = tid >> 4;
    const int row0 = blockIdx.y * 128, col0 = blockIdx.x * 128;
    const int lm = tid >> 1;
    const int lk = (tid & 1) * 4;
    float acc[8][8];
#pragma unroll
    for (int i = 0; i < 8; i++)
#pragma unroll
        for (int j = 0; j < 8; j++) acc[i][j] = 0.f;

    const int gmA = row0 + lm;
    const int gnB = col0 + lm;
    for (int k0 = 0; k0 < K; k0 += 8) {
#pragma unroll
        for (int j = 0; j < 4; j++) {
            int gk = k0 + lk + j;
            As[lk + j][lm] = (gmA < M && gk < K) ? A[(size_t)gmA * lda + gk] : 0.f;
            Bs[lk + j][lm] = (gnB < N && gk < K) ? B[(size_t)gnB * ldb + gk] : 0.f;
        }
        __syncthreads();
#pragma unroll
        for (int kk = 0; kk < 8; kk++) {
            float a[8], bb[8];
#pragma unroll
            for (int i = 0; i < 8; i++) a[i] = As[kk][ty * 8 + i];
#pragma unroll
            for (int j = 0; j < 8; j++) bb[j] = Bs[kk][tx * 8 + j];
#pragma unroll
            for (int i = 0; i < 8; i++)
#pragma unroll
                for (int j = 0; j < 8; j++) acc[i][j] = fmaf(a[i], bb[j], acc[i][j]);
        }
        __syncthreads();
    }
#pragma unroll
    for (int i = 0; i < 8; i++) {
        int gm = row0 + ty * 8 + i;
        if (gm >= M) continue;
#pragma unroll
        for (int j = 0; j < 8; j++) {
            int gn = col0 + tx * 8 + j;
            if (gn >= N) continue;
            float v = acc[i][j];
            v = v * aux1[gn] + aux2[gn];
            v = fminf(fmaxf(v, 0.f), 6.f);
            C[(size_t)gm * ldc + gn] = v;
        }
    }
}

__global__ void k_reduce0() {
    int b = blockIdx.x, d = threadIdx.x;
    float acc = 0.f;
    for (int l = 0; l < 256; l++)
        acc += g_tmp0[((size_t)(b * 256 + l)) * 128 + d];
    g_y0[b * 128 + d] = acc * (1.f / 256.f);
}

__global__ void k_pool() {
    int b = blockIdx.x;
    int spg = blockIdx.y;
    int s, row_base, local;
    if (spg < 25)       { s = 5;  row_base = 0;    local = spg; }
    else if (spg < 106) { s = 9;  row_base = 1600; local = spg - 25; }
    else                { s = 13; row_base = 6784; local = spg - 106; }
    int o = local / s, p = local % s;
    int h0 = (o * 16) / s, h1 = ((o + 1) * 16 + s - 1) / s;
    int w0 = (p * 16) / s, w1 = ((p + 1) * 16 + s - 1) / s;
    float wgt = 1.f / (float)((h1 - h0) * (w1 - w0));
    size_t orow = (size_t)(row_base + b * s * s + local) * COMBC;
    for (int c = threadIdx.x; c < COMBC; c += 256) {
        float acc = 0.f;
        for (int h = h0; h < h1; h++)
            for (int w = w0; w < w1; w++)
                acc += g_seq[((size_t)(b * 256 + h * 16 + w)) * LDSEQ + c];
        g_pooled[orow + c] = acc * wgt;
    }
}

__global__ void k_assemble() {
    int m = blockIdx.x;
    int b = m >> 8, l = m & 255;
    int o = l >> 4, p = l & 15;
    int t = threadIdx.x;
    if (t < 30) g_seq[(size_t)m * LDSEQ + 1282 + t] = 0.f;  // zero K-pad
    if (t < 128) {
        g_seq[(size_t)m * LDSEQ + 770 + t] = g_y0[b * 128 + t];
    } else {
        int i = (t - 128) >> 7;
        int d = (t - 128) & 127;
        int s      = (i == 0) ? 5 : (i == 1) ? 9 : 13;
        int base_r = (i == 0) ? 0 : (i == 1) ? 1600 : 6784;
        float fs = (float)s;
        float so = (o + 0.5f) * fs / 16.0f - 0.5f;
        so = fminf(fmaxf(so, 0.f), fs - 1.0f);
        int h0 = (int)floorf(so); int h1 = min(h0 + 1, s - 1); float fo = so - (float)h0;
        float sp = (p + 0.5f) * fs / 16.0f - 0.5f;
        sp = fminf(fmaxf(sp, 0.f), fs - 1.0f);
        int w0 = (int)floorf(sp); int w1 = min(w0 + 1, s - 1); float fp = sp - (float)w0;
        const float* yb = g_yp + (size_t)(base_r + b * s * s) * 128 + d;
        float v00 = yb[(size_t)(h0 * s + w0) * 128];
        float v01 = yb[(size_t)(h0 * s + w1) * 128];
        float v10 = yb[(size_t)(h1 * s + w0) * 128];
        float v11 = yb[(size_t)(h1 * s + w1) * 128];
        float v = (1.f - fo) * ((1.f - fp) * v00 + fp * v01)
                + fo * ((1.f - fp) * v10 + fp * v11);
        g_seq[(size_t)m * LDSEQ + 898 + i * 128 + d] = v;
    }
}

// depthwise causal conv1d + bias + SiLU; writes fp32 g_u AND hi/lo g_uhl
__global__ void k_conv1d(const float* __restrict__ w, const float* __restrict__ bias) {
    int m = blockIdx.x;
    int d = blockIdx.y * 256 + threadIdx.x;
    if (d >= 2592) return;
    size_t hb = ((size_t)m * 81 + (d >> 5)) * 64 + (d & 31);
    if (d >= DINNER) {   // zero pads
        g_uhl[hb] = __float2bfloat16(0.f);
        g_uhl[hb + 32] = __float2bfloat16(0.f);
        return;
    }
    int l = m & 255;
    size_t base = (size_t)m * (2 * DINNER) + d;
    float acc = bias[d];
    const float* wd = w + d * 4;
#pragma unroll
    for (int j = 0; j < 4; j++) {
        int l2 = l - 3 + j;
        if (l2 >= 0) acc += wd[j] * g_xz[base + (size_t)(j - 3) * (2 * DINNER)];
    }
    float v = acc / (1.f + __expf(-acc));
    g_u[(size_t)m * DINNER + d] = v;
    __nv_bfloat16 hi = __float2bfloat16(v);
    g_uhl[hb] = hi;
    g_uhl[hb + 32] = __float2bfloat16(v - __bfloat162float(hi));
}

// selective scan; writes hi/lo g_yshl directly
__global__ __launch_bounds__(256) void k_scan(const float* __restrict__ A_log,
                                              const float* __restrict__ Dp) {
    int b = blockIdx.y;
    int d = blockIdx.x * 256 + threadIdx.x;
    if (d >= DINNER) {
        if (d < 2592) {
            for (int l = 0; l < 256; l++) {
                size_t hb = ((size_t)(b * 256 + l) * 81 + (d >> 5)) * 64 + (d & 31);
                g_yshl[hb] = __float2bfloat16(0.f);
                g_yshl[hb + 32] = __float2bfloat16(0.f);
            }
        }
        return;
    }
    float A[DSTATE];
#pragma unroll
    for (int n = 0; n < DSTATE; n++) A[n] = -__expf(A_log[d * DSTATE + n]);
    float Dd = Dp[d];
    float h[DSTATE];
#pragma unroll
    for (int n = 0; n < DSTATE; n++) h[n] = 0.f;

    const float* dtp = g_dtv + (size_t)b * 256 * DINNER + d;
    const float* up  = g_u   + (size_t)b * 256 * DINNER + d;
    const float* zp  = g_xz  + (size_t)b * 256 * (2 * DINNER) + DINNER + d;
    const float* bc  = g_dbl + (size_t)b * 256 * DBL_LD;
    const int cj = (d >> 5) * 64 + (d & 31);

    for (int l = 0; l < 256; l++) {
        float dt = dtp[(size_t)l * DINNER];
        float u  = up [(size_t)l * DINNER];
        const float4* bcrow = reinterpret_cast<const float4*>(bc + (size_t)l * DBL_LD + 84);
        float4 Bv0 = bcrow[0], Bv1 = bcrow[1], Bv2 = bcrow[2], Bv3 = bcrow[3];
        float4 Cv0 = bcrow[4], Cv1 = bcrow[5], Cv2 = bcrow[6], Cv3 = bcrow[7];
        float Bm[16] = {Bv0.x,Bv0.y,Bv0.z,Bv0.w, Bv1.x,Bv1.y,Bv1.z,Bv1.w,
                        Bv2.x,Bv2.y,Bv2.z,Bv2.w, Bv3.x,Bv3.y,Bv3.z,Bv3.w};
        float Cm[16] = {Cv0.x,Cv0.y,Cv0.z,Cv0.w, Cv1.x,Cv1.y,Cv1.z,Cv1.w,
                        Cv2.x,Cv2.y,Cv2.z,Cv2.w, Cv3.x,Cv3.y,Cv3.z,Cv3.w};
        float xbu = dt * u;
        float y = 0.f;
#pragma unroll
        for (int n = 0; n < DSTATE; n++) {
            float dA = __expf(dt * A[n]);
            h[n] = dA * h[n] + xbu * Bm[n];
            y += h[n] * Cm[n];
        }
        float z = zp[(size_t)l * (2 * DINNER)];
        float sil = z / (1.f + __expf(-z));
        float v = (y + u * Dd) * sil;
        size_t hb = ((size_t)(b * 256 + l) * 81) * 64 + cj;
        __nv_bfloat16 hi = __float2bfloat16(v);
        g_yshl[hb] = hi;
        g_yshl[hb + 32] = __float2bfloat16(v - __bfloat162float(hi));
    }
}

// ================= launch =================
extern "C" void kernel_launch(void* const* d_in, const int* in_sizes, int n_in,
                              void* d_out, int out_size) {
    (void)in_sizes; (void)n_in; (void)out_size;
    const float* x         = (const float*)d_in[0];
    const float* pc_emb    = (const float*)d_in[1];
    const float* conv_w    = (const float*)d_in[2];
    const float* bn_gamma  = (const float*)d_in[3];
    const float* bn_beta   = (const float*)d_in[4];
    const float* bn_mean   = (const float*)d_in[5];
    const float* bn_var    = (const float*)d_in[6];
    const float* in_proj_w = (const float*)d_in[7];
    const float* conv1d_w  = (const float*)d_in[8];
    const float* conv1d_b  = (const float*)d_in[9];
    const float* x_proj_w  = (const float*)d_in[10];
    const float* dt_proj_w = (const float*)d_in[11];
    const float* dt_proj_b = (const float*)d_in[12];
    const float* A_log     = (const float*)d_in[13];
    const float* Dvec      = (const float*)d_in[14];
    const float* out_proj_w= (const float*)d_in[15];
    float* out = (float*)d_out;

    float *p_seq, *p_tmp0, *p_pooled, *p_yp, *p_xz, *p_dbl, *p_dtv, *p_bn;
    __nv_bfloat16 *p_seqhl, *p_winhl, *p_uhl, *p_xwhl, *p_dblhl, *p_dtwhl, *p_yshl, *p_wouthl;
    cudaGetSymbolAddress((void**)&p_seq,    g_seq);
    cudaGetSymbolAddress((void**)&p_tmp0,   g_tmp0);
    cudaGetSymbolAddress((void**)&p_pooled, g_pooled);
    cudaGetSymbolAddress((void**)&p_yp,     g_yp);
    cudaGetSymbolAddress((void**)&p_xz,     g_xz);
    cudaGetSymbolAddress((void**)&p_dbl,    g_dbl);
    cudaGetSymbolAddress((void**)&p_dtv,    g_dtv);
    cudaGetSymbolAddress((void**)&p_bn,     g_bn);
    cudaGetSymbolAddress((void**)&p_seqhl,  g_seqhl);
    cudaGetSymbolAddress((void**)&p_winhl,  g_winhl);
    cudaGetSymbolAddress((void**)&p_uhl,    g_uhl);
    cudaGetSymbolAddress((void**)&p_xwhl,   g_xwhl);
    cudaGetSymbolAddress((void**)&p_dblhl,  g_dblhl);
    cudaGetSymbolAddress((void**)&p_dtwhl,  g_dtwhl);
    cudaGetSymbolAddress((void**)&p_yshl,   g_yshl);
    cudaGetSymbolAddress((void**)&p_wouthl, g_wouthl);

    cudaFuncSetAttribute(wgemm2<0>, cudaFuncAttributeMaxDynamicSharedMemorySize, WS2);
    cudaFuncSetAttribute(wgemm2<1>, cudaFuncAttributeMaxDynamicSharedMemorySize, WS2);
    cudaFuncSetAttribute(wgemm2<2>, cudaFuncAttributeMaxDynamicSharedMemorySize, WS2);
    cudaFuncSetAttribute(wgemm2<3>, cudaFuncAttributeMaxDynamicSharedMemorySize, WS2);

    // weight converts (independent of data path)
    k_cvt<<<(5248*41*16 + 255)/256, 256>>>(in_proj_w,  p_winhl,  5128, 1282, 1282, 41, 5248*41*16);
    k_cvt<<<(1408*81*16 + 255)/256, 256>>>(out_proj_w, p_wouthl, 1282, 2564, 2564, 81, 1408*81*16);
    k_cvt<<<(128*81*16  + 255)/256, 256>>>(x_proj_w,   p_xwhl,    113, 2564, 2564, 81, 128*81*16);
    k_cvt<<<(2688*3*16  + 255)/256, 256>>>(dt_proj_w,  p_dtwhl,  2564,   81,   81,  3, 2688*3*16);

    // PPM
    k_bnprep<<<1, 512>>>(bn_gamma, bn_beta, bn_mean, bn_var);
    k_build<<<dim3(64, 25, 8), dim3(32, 32)>>>(x, pc_emb);
    sgemm<1><<<dim3(1, 128), 256>>>(p_seq, conv_w, p_tmp0,
                                    MSEQ, 128, COMBC, LDSEQ, COMBC, 128, p_bn, p_bn + 512);
    k_reduce0<<<64, 128>>>();
    k_pool<<<dim3(64, 275), 256>>>();
    sgemm<1><<<dim3(1, 13), 256>>>(p_pooled, conv_w + 1 * 128 * COMBC, p_yp,
                                   1600, 128, COMBC, COMBC, COMBC, 128,
                                   p_bn + 128, p_bn + 512 + 128);
    sgemm<1><<<dim3(1, 41), 256>>>(p_pooled + (size_t)1600 * COMBC, conv_w + 2 * 128 * COMBC,
                                   p_yp + (size_t)1600 * 128,
                                   5184, 128, COMBC, COMBC, COMBC, 128,
                                   p_bn + 256, p_bn + 512 + 256);
    sgemm<1><<<dim3(1, 85), 256>>>(p_pooled + (size_t)6784 * COMBC, conv_w + 3 * 128 * COMBC,
                                   p_yp + (size_t)6784 * 128,
                                   10816, 128, COMBC, COMBC, COMBC, 128,
                                   p_bn + 384, p_bn + 512 + 384);
    k_assemble<<<MSEQ, 512>>>();
    k_cvt<<<(MSEQ*41*16 + 255)/256, 256>>>(p_seq, p_seqhl, MSEQ, 1312, LDSEQ, 41, MSEQ*41*16);

    // Mamba
    wgemm2<0><<<dim3(41, 128), 256, WS2>>>(p_seqhl, p_winhl, p_xz, 5128, 5128, 41, nullptr);
    k_conv1d<<<dim3(MSEQ, 11), 256>>>(conv1d_w, conv1d_b);
    wgemm2<2><<<dim3(1, 128),  256, WS2>>>(p_uhl, p_xwhl, p_dbl, 113, 0, 81, nullptr);
    wgemm2<3><<<dim3(21, 128), 256, WS2>>>(p_dblhl, p_dtwhl, p_dtv, DINNER, 0, 3, dt_proj_b);
    k_scan<<<dim3(11, 64), 256>>>(A_log, Dvec);
    wgemm2<1><<<dim3(11, 128), 256, WS2>>>(p_yshl, p_wouthl, out, DMODEL, 0, 81, nullptr);
}

// round 15
// speedup vs baseline: 2.9302x; 1.0484x over previous
#include <cuda_runtime.h>
#include <cuda_bf16.h>
#include <math.h>
#include <stdint.h>

#define BB 64
#define COMBC 770
#define DMODEL 1282
#define DINNER 2564
#define DSTATE 16
#define MSEQ 16384
#define LDSEQ 1312      // padded d_model (41*32)
#define DBL_LD 116

// ---------------- scratch (device globals; no allocations allowed) ----------------
__device__ __align__(128) float g_seq[(size_t)MSEQ * LDSEQ];     // padded, pad cols zeroed
__device__ __align__(128) float g_tmp0[(size_t)MSEQ * 128];
__device__ __align__(128) float g_y0[BB * 128];
__device__ __align__(128) float g_pooled[(size_t)17600 * COMBC];
__device__ __align__(128) float g_yp[(size_t)17600 * 128];
__device__ __align__(128) float g_xz[(size_t)MSEQ * 2 * DINNER];
__device__ __align__(128) float g_u[(size_t)MSEQ * DINNER];
__device__ __align__(128) float g_dbl[(size_t)MSEQ * DBL_LD];
__device__ __align__(128) float g_dtv[(size_t)MSEQ * DINNER];
__device__ __align__(128) float g_bn[1024];

// hi/lo bf16 chunk-interleaved operands: [(m*nch + c)*64 + j], j<32 hi(k=c*32+j), j>=32 lo
__device__ __align__(128) __nv_bfloat16 g_seqhl [(size_t)MSEQ * 41 * 64];
__device__ __align__(128) __nv_bfloat16 g_winhl [(size_t)5248 * 41 * 64];
__device__ __align__(128) __nv_bfloat16 g_uhl   [(size_t)MSEQ * 81 * 64];
__device__ __align__(128) __nv_bfloat16 g_xwhl  [(size_t)128  * 81 * 64];
__device__ __align__(128) __nv_bfloat16 g_dblhl [(size_t)MSEQ * 3  * 64];
__device__ __align__(128) __nv_bfloat16 g_dtwhl [(size_t)2688 * 3  * 64];
__device__ __align__(128) __nv_bfloat16 g_yshl  [(size_t)MSEQ * 81 * 64];
__device__ __align__(128) __nv_bfloat16 g_wouthl[(size_t)1408 * 81 * 64];
__device__ __align__(128) __nv_bfloat16 g_combhl[(size_t)MSEQ * 25 * 64];
__device__ __align__(128) __nv_bfloat16 g_cw0hl [(size_t)128  * 25 * 64];

// ================= helpers =================
__device__ __forceinline__ uint32_t smem_u32(const void* p) {
    uint32_t a;
    asm("{ .reg .u64 t; cvta.to.shared.u64 t, %1; cvt.u32.u64 %0, t; }" : "=r"(a) : "l"(p));
    return a;
}
__device__ __forceinline__ void ldsm4(uint32_t& r0, uint32_t& r1, uint32_t& r2, uint32_t& r3,
                                      uint32_t addr) {
    asm volatile("ldmatrix.sync.aligned.m8n8.x4.shared.b16 {%0,%1,%2,%3}, [%4];"
                 : "=r"(r0), "=r"(r1), "=r"(r2), "=r"(r3) : "r"(addr));
}
__device__ __forceinline__ void mma_bf16(float* d, const uint32_t* a, const uint32_t* b) {
    asm volatile(
        "mma.sync.aligned.m16n8k16.row.col.f32.bf16.bf16.f32 "
        "{%0,%1,%2,%3}, {%4,%5,%6,%7}, {%8,%9}, {%0,%1,%2,%3};"
        : "+f"(d[0]), "+f"(d[1]), "+f"(d[2]), "+f"(d[3])
        : "r"(a[0]), "r"(a[1]), "r"(a[2]), "r"(a[3]), "r"(b[0]), "r"(b[1]));
}
__device__ __forceinline__ void split2(float x, float y, __nv_bfloat162& hi, __nv_bfloat162& lo) {
    hi.x = __float2bfloat16(x); hi.y = __float2bfloat16(y);
    lo.x = __float2bfloat16(x - __bfloat162float(hi.x));
    lo.y = __float2bfloat16(y - __bfloat162float(hi.y));
}
__device__ __forceinline__ void cpasync16(uint32_t s, const void* g) {
    asm volatile("cp.async.cg.shared.global [%0], [%1], 16;" :: "r"(s), "l"(g));
}
#define CP_COMMIT() asm volatile("cp.async.commit_group;" ::: "memory")
#define CP_WAIT1()  asm volatile("cp.async.wait_group 1;" ::: "memory")

// ---------------- generic fp32 -> hi/lo chunked convert ----------------
__global__ void k_cvt(const float* __restrict__ src, __nv_bfloat16* __restrict__ dst,
                      int Mreal, int Kreal, int lds, int nch, int total) {
    int i = blockIdx.x * 256 + threadIdx.x;
    if (i >= total) return;
    int jp = i & 15;
    int t = i >> 4;
    int c = t % nch;
    int m = t / nch;
    int k = c * 32 + jp * 2;
    float f0 = 0.f, f1 = 0.f;
    if (m < Mreal) {
        if (k < Kreal)     f0 = src[(size_t)m * lds + k];
        if (k + 1 < Kreal) f1 = src[(size_t)m * lds + k + 1];
    }
    __nv_bfloat162 hi, lo;
    split2(f0, f1, hi, lo);
    size_t base = ((size_t)(m * nch + c)) * 64 + jp * 2;
    *(__nv_bfloat162*)&dst[base]      = hi;
    *(__nv_bfloat162*)&dst[base + 32] = lo;
}

// ===== wgemm2: cp.async-pipelined bf16-split GEMM on pre-converted hi/lo operands =====
// C[m,n] = sum_k A[m,k]*B[n,k]. 128x128 tile, 3 stages x 32KB.
// EPI: 0 plain(ldc), 1 (b,n,l) store, 2 x_proj (remap fp32 + dbl_hl), 3 bias+softplus,
//      4 BN+ReLU6 (aux: inv[512..] add), ldc
#define WS2 98304

template<int EPI>
__global__ __launch_bounds__(256, 2) void wgemm2(
    const __nv_bfloat16* __restrict__ Ahl, const __nv_bfloat16* __restrict__ Bhl,
    float* __restrict__ C, int Nreal, int ldc, int nch, const float* __restrict__ aux)
{
    extern __shared__ char smem[];
    const int tid = threadIdx.x;
    const int wid = tid >> 5;
    const int lane = tid & 31;
    const int wm = wid >> 2, wn = wid & 3;
    const int row0 = blockIdx.y * 128;
    const int col0 = blockIdx.x * 128;
    const uint32_t sb = smem_u32(smem);

    // cp.async per-thread mapping (4 x 16B per operand per stage)
    const int cp_r0 = tid >> 3, cp_c8 = tid & 7;
    const uint32_t cp_sw = (uint32_t)((cp_c8 ^ (cp_r0 & 7)) << 4);

    auto issue = [&](int c, int s) {
        const uint32_t st = sb + s * 32768;
        const size_t ga = ((size_t)(row0 + cp_r0) * nch + c) * 64 + cp_c8 * 8;
        const size_t gb = ((size_t)(col0 + cp_r0) * nch + c) * 64 + cp_c8 * 8;
#pragma unroll
        for (int q = 0; q < 4; q++) {
            uint32_t so = (uint32_t)((cp_r0 + q * 32) * 128) + cp_sw;
            cpasync16(st + so,         Ahl + ga + (size_t)q * 32 * nch * 64);
            cpasync16(st + 16384 + so, Bhl + gb + (size_t)q * 32 * nch * 64);
        }
    };

    // fragment addressing
    const int r3 = lane & 7;
    const uint32_t aRowB = (uint32_t)((wm * 64 + r3 + ((lane >> 3) & 1) * 8) * 128);
    const int aSel = (lane >> 4) & 1;
    const uint32_t bRowB = (uint32_t)(16384 + (wn * 32 + r3 + ((lane >> 4) & 1) * 8) * 128);
    const int bSel = (lane >> 3) & 1;

    float acc[4][4][4];
#pragma unroll
    for (int i = 0; i < 4; i++)
#pragma unroll
        for (int j = 0; j < 4; j++)
#pragma unroll
            for (int q = 0; q < 4; q++) acc[i][j][q] = 0.f;

    issue(0, 0); CP_COMMIT();
    if (nch > 1) issue(1, 1);
    CP_COMMIT();

    for (int c = 0; c < nch; c++) {
        const int s = c % 3;
        CP_WAIT1();
        __syncthreads();
        if (c + 2 < nch) issue(c + 2, (c + 2) % 3);
        CP_COMMIT();
        const uint32_t st = sb + s * 32768;
#pragma unroll
        for (int kk2 = 0; kk2 < 2; kk2++) {
            const int aCh = aSel + kk2 * 2;
            const uint32_t aHi = (uint32_t)((aCh ^ r3) << 4);
            const uint32_t aLo = (uint32_t)(((aCh + 4) ^ r3) << 4);
            const int bCh = bSel + kk2 * 2;
            const uint32_t bHi = (uint32_t)((bCh ^ r3) << 4);
            const uint32_t bLo = (uint32_t)(((bCh + 4) ^ r3) << 4);
            uint32_t bfh[4][2], bfl[4][2];
#pragma unroll
            for (int ntp = 0; ntp < 2; ntp++) {
                uint32_t ba = st + bRowB + ntp * 2048;
                ldsm4(bfh[ntp*2][0], bfh[ntp*2][1], bfh[ntp*2+1][0], bfh[ntp*2+1][1], ba + bHi);
                ldsm4(bfl[ntp*2][0], bfl[ntp*2][1], bfl[ntp*2+1][0], bfl[ntp*2+1][1], ba + bLo);
            }
            // process mt in pairs: 3 pass-sweeps of 8 independent MMAs each
#pragma unroll
            for (int mp = 0; mp < 2; mp++) {
                uint32_t afh[2][4], afl[2][4];
#pragma unroll
                for (int m2 = 0; m2 < 2; m2++) {
                    uint32_t aa = st + aRowB + (mp * 2 + m2) * 2048;
                    ldsm4(afh[m2][0], afh[m2][1], afh[m2][2], afh[m2][3], aa + aHi);
                    ldsm4(afl[m2][0], afl[m2][1], afl[m2][2], afl[m2][3], aa + aLo);
                }
#pragma unroll
                for (int m2 = 0; m2 < 2; m2++)
#pragma unroll
                    for (int nt = 0; nt < 4; nt++)
                        mma_bf16(acc[mp*2+m2][nt], afh[m2], bfh[nt]);
#pragma unroll
                for (int m2 = 0; m2 < 2; m2++)
#pragma unroll
                    for (int nt = 0; nt < 4; nt++)
                        mma_bf16(acc[mp*2+m2][nt], afl[m2], bfh[nt]);
#pragma unroll
                for (int m2 = 0; m2 < 2; m2++)
#pragma unroll
                    for (int nt = 0; nt < 4; nt++)
                        mma_bf16(acc[mp*2+m2][nt], afh[m2], bfl[nt]);
            }
        }
    }

    // ---- epilogue ----
    const int g = lane >> 2, tq = lane & 3;
#pragma unroll
    for (int mt = 0; mt < 4; mt++) {
        const int m = row0 + wm * 64 + mt * 16 + g;
#pragma unroll
        for (int nt = 0; nt < 4; nt++) {
            const int n = col0 + wn * 32 + nt * 8 + tq * 2;
            float* a4 = acc[mt][nt];
            if (EPI == 0) {
                if (n < Nreal) {
                    *(float2*)&C[(size_t)m * ldc + n] = make_float2(a4[0], a4[1]);
                    *(float2*)&C[(size_t)(m + 8) * ldc + n] = make_float2(a4[2], a4[3]);
                }
            } else if (EPI == 1) {
                if (n < Nreal) {
                    size_t ob = ((size_t)(m >> 8) * DMODEL + n) * 256 + (m & 255);
                    C[ob] = a4[0]; C[ob + 256] = a4[1];
                    C[ob + 8] = a4[2]; C[ob + 256 + 8] = a4[3];
                }
            } else if (EPI == 2) {
#pragma unroll
                for (int e = 0; e < 4; e++) {
                    int nn = n + (e & 1), mm = m + (e >> 1) * 8;
                    float v = a4[e];
                    if (nn < 81)       C[(size_t)mm * DBL_LD + nn] = v;
                    else if (nn < 113) C[(size_t)mm * DBL_LD + nn + 3] = v;
                    if (nn < 96) {
                        float vv = (nn < 81) ? v : 0.f;
                        __nv_bfloat16 hi = __float2bfloat16(vv);
                        __nv_bfloat16 lo = __float2bfloat16(vv - __bfloat162float(hi));
                        size_t hb = ((size_t)mm * 3 + (nn >> 5)) * 64 + (nn & 31);
                        g_dblhl[hb] = hi; g_dblhl[hb + 32] = lo;
                    }
                }
            } else if (EPI == 3) {
#pragma unroll
                for (int e = 0; e < 4; e++) {
                    int nn = n + (e & 1), mm = m + (e >> 1) * 8;
                    if (nn < Nreal) {
                        float v = a4[e] + aux[nn];
                        v = (v > 20.f) ? v : log1pf(__expf(v));
                        C[(size_t)mm * DINNER + nn] = v;
                    }
                }
            } else {
#pragma unroll
                for (int e = 0; e < 4; e++) {
                    int nn = n + (e & 1), mm = m + (e >> 1) * 8;
                    if (nn < Nreal) {
                        float v = a4[e] * aux[nn] + aux[512 + nn];
                        v = fminf(fmaxf(v, 0.f), 6.f);
                        C[(size_t)mm * ldc + nn] = v;
                    }
                }
            }
        }
    }
}

// ================= SIMT pieces =================
__global__ void k_bnprep(const float* __restrict__ gamma, const float* __restrict__ beta,
                         const float* __restrict__ mean, const float* __restrict__ var) {
    int i = threadIdx.x;
    if (i < 512) {
        float inv = rsqrtf(var[i] + 1e-5f) * gamma[i];
        g_bn[i] = inv;
        g_bn[512 + i] = beta[i] - mean[i] * inv;
    }
}

__device__ __forceinline__ float xx_val(int i) { return -0.3f + (0.6f / 15.0f) * (float)i; }

__global__ void k_build(const float* __restrict__ x, const float* __restrict__ pc) {
    __shared__ float tile[32][33];
    int b = blockIdx.x;
    int c0 = blockIdx.y * 32;
    int l0 = blockIdx.z * 32;
    int tx = threadIdx.x, ty = threadIdx.y;
    int c = c0 + ty, l = l0 + tx;
    if (c < COMBC) {
        float v;
        if (c < 512)       v = x[((size_t)(b * 512 + c)) * 256 + l];
        else if (c == 512) v = xx_val(l & 15);
        else if (c == 513) v = xx_val(l >> 4);
        else               v = pc[b * 256 + (c - 514)];
        tile[ty][tx] = v;
    }
    __syncthreads();
    c = c0 + tx; l = l0 + ty;
    if (c < COMBC)
        g_seq[((size_t)(b * 256 + l)) * LDSEQ + c] = tile[tx][ty];
}

// SIMT SGEMM (small pooled PPM convs only). EP=1: BN+ReLU6
template<int EP>
__global__ __launch_bounds__(256, 2) void sgemm(
    const float* __restrict__ A, const float* __restrict__ B, float* __restrict__ C,
    int M, int N, int K, int lda, int ldb, int ldc,
    const float* __restrict__ aux1, const float* __restrict__ aux2)
{
    __shared__ float As[8][128];
    __shared__ float Bs[8][128];
    const int tid = threadIdx.x;
    const int tx = tid & 15, ty = tid >> 4;
    const int row0 = blockIdx.y * 128, col0 = blockIdx.x * 128;
    const int lm = tid >> 1;
    const int lk = (tid & 1) * 4;
    float acc[8][8];
#pragma unroll
    for (int i = 0; i < 8; i++)
#pragma unroll
        for (int j = 0; j < 8; j++) acc[i][j] = 0.f;

    const int gmA = row0 + lm;
    const int gnB = col0 + lm;
    for (int k0 = 0; k0 < K; k0 += 8) {
#pragma unroll
        for (int j = 0; j < 4; j++) {
            int gk = k0 + lk + j;
            As[lk + j][lm] = (gmA < M && gk < K) ? A[(size_t)gmA * lda + gk] : 0.f;
            Bs[lk + j][lm] = (gnB < N && gk < K) ? B[(size_t)gnB * ldb + gk] : 0.f;
        }
        __syncthreads();
#pragma unroll
        for (int kk = 0; kk < 8; kk++) {
            float a[8], bb[8];
#pragma unroll
            for (int i = 0; i < 8; i++) a[i] = As[kk][ty * 8 + i];
#pragma unroll
            for (int j = 0; j < 8; j++) bb[j] = Bs[kk][tx * 8 + j];
#pragma unroll
            for (int i = 0; i < 8; i++)
#pragma unroll
                for (int j = 0; j < 8; j++) acc[i][j] = fmaf(a[i], bb[j], acc[i][j]);
        }
        __syncthreads();
    }
#pragma unroll
    for (int i = 0; i < 8; i++) {
        int gm = row0 + ty * 8 + i;
        if (gm >= M) continue;
#pragma unroll
        for (int j = 0; j < 8; j++) {
            int gn = col0 + tx * 8 + j;
            if (gn >= N) continue;
            float v = acc[i][j];
            v = v * aux1[gn] + aux2[gn];
            v = fminf(fmaxf(v, 0.f), 6.f);
            C[(size_t)gm * ldc + gn] = v;
        }
    }
}

__global__ void k_reduce0() {
    int b = blockIdx.x, d = threadIdx.x;
    float acc = 0.f;
    for (int l = 0; l < 256; l++)
        acc += g_tmp0[((size_t)(b * 256 + l)) * 128 + d];
    g_y0[b * 128 + d] = acc * (1.f / 256.f);
}

__global__ void k_pool() {
    int b = blockIdx.x;
    int spg = blockIdx.y;
    int s, row_base, local;
    if (spg < 25)       { s = 5;  row_base = 0;    local = spg; }
    else if (spg < 106) { s = 9;  row_base = 1600; local = spg - 25; }
    else                { s = 13; row_base = 6784; local = spg - 106; }
    int o = local / s, p = local % s;
    int h0 = (o * 16) / s, h1 = ((o + 1) * 16 + s - 1) / s;
    int w0 = (p * 16) / s, w1 = ((p + 1) * 16 + s - 1) / s;
    float wgt = 1.f / (float)((h1 - h0) * (w1 - w0));
    size_t orow = (size_t)(row_base + b * s * s + local) * COMBC;
    for (int c = threadIdx.x; c < COMBC; c += 256) {
        float acc = 0.f;
        for (int h = h0; h < h1; h++)
            for (int w = w0; w < w1; w++)
                acc += g_seq[((size_t)(b * 256 + h * 16 + w)) * LDSEQ + c];
        g_pooled[orow + c] = acc * wgt;
    }
}

__global__ void k_assemble() {
    int m = blockIdx.x;
    int b = m >> 8, l = m & 255;
    int o = l >> 4, p = l & 15;
    int t = threadIdx.x;
    if (t < 30) g_seq[(size_t)m * LDSEQ + 1282 + t] = 0.f;  // zero K-pad
    if (t < 128) {
        g_seq[(size_t)m * LDSEQ + 770 + t] = g_y0[b * 128 + t];
    } else {
        int i = (t - 128) >> 7;
        int d = (t - 128) & 127;
        int s      = (i == 0) ? 5 : (i == 1) ? 9 : 13;
        int base_r = (i == 0) ? 0 : (i == 1) ? 1600 : 6784;
        float fs = (float)s;
        float so = (o + 0.5f) * fs / 16.0f - 0.5f;
        so = fminf(fmaxf(so, 0.f), fs - 1.0f);
        int h0 = (int)floorf(so); int h1 = min(h0 + 1, s - 1); float fo = so - (float)h0;
        float sp = (p + 0.5f) * fs / 16.0f - 0.5f;
        sp = fminf(fmaxf(sp, 0.f), fs - 1.0f);
        int w0 = (int)floorf(sp); int w1 = min(w0 + 1, s - 1); float fp = sp - (float)w0;
        const float* yb = g_yp + (size_t)(base_r + b * s * s) * 128 + d;
        float v00 = yb[(size_t)(h0 * s + w0) * 128];
        float v01 = yb[(size_t)(h0 * s + w1) * 128];
        float v10 = yb[(size_t)(h1 * s + w0) * 128];
        float v11 = yb[(size_t)(h1 * s + w1) * 128];
        float v = (1.f - fo) * ((1.f - fp) * v00 + fp * v01)
                + fo * ((1.f - fp) * v10 + fp * v11);
        g_seq[(size_t)m * LDSEQ + 898 + i * 128 + d] = v;
    }
}

// depthwise causal conv1d + bias + SiLU; sliding window over l, one thread per (b,d)
__global__ void k_conv1d(const float* __restrict__ w, const float* __restrict__ bias) {
    int b = blockIdx.x;
    int d = blockIdx.y * 256 + threadIdx.x;
    if (d >= 2592) return;
    if (d >= DINNER) {   // zero pads
        __nv_bfloat16 z = __float2bfloat16(0.f);
        for (int l = 0; l < 256; l++) {
            size_t hb = ((size_t)(b * 256 + l) * 81 + (d >> 5)) * 64 + (d & 31);
            g_uhl[hb] = z; g_uhl[hb + 32] = z;
        }
        return;
    }
    float w0 = w[d * 4], w1 = w[d * 4 + 1], w2 = w[d * 4 + 2], w3 = w[d * 4 + 3];
    float bs = bias[d];
    float x0 = 0.f, x1 = 0.f, x2 = 0.f;
    const float* xp = g_xz + (size_t)b * 256 * (2 * DINNER) + d;
    float* up = g_u + (size_t)b * 256 * DINNER + d;
    const int cj = (d >> 5) * 64 + (d & 31);
#pragma unroll 4
    for (int l = 0; l < 256; l++) {
        float x3 = xp[(size_t)l * (2 * DINNER)];
        float acc = bs + w0 * x0 + w1 * x1 + w2 * x2 + w3 * x3;
        x0 = x1; x1 = x2; x2 = x3;
        float v = acc / (1.f + __expf(-acc));
        up[(size_t)l * DINNER] = v;
        size_t hb = ((size_t)(b * 256 + l) * 81) * 64 + cj;
        __nv_bfloat16 hi = __float2bfloat16(v);
        g_uhl[hb] = hi;
        g_uhl[hb + 32] = __float2bfloat16(v - __bfloat162float(hi));
    }
}

// selective scan; writes hi/lo g_yshl directly
__global__ __launch_bounds__(256) void k_scan(const float* __restrict__ A_log,
                                              const float* __restrict__ Dp) {
    int b = blockIdx.y;
    int d = blockIdx.x * 256 + threadIdx.x;
    if (d >= DINNER) {
        if (d < 2592) {
            for (int l = 0; l < 256; l++) {
                size_t hb = ((size_t)(b * 256 + l) * 81 + (d >> 5)) * 64 + (d & 31);
                g_yshl[hb] = __float2bfloat16(0.f);
                g_yshl[hb + 32] = __float2bfloat16(0.f);
            }
        }
        return;
    }
    float A[DSTATE];
#pragma unroll
    for (int n = 0; n < DSTATE; n++) A[n] = -__expf(A_log[d * DSTATE + n]);
    float Dd = Dp[d];
    float h[DSTATE];
#pragma unroll
    for (int n = 0; n < DSTATE; n++) h[n] = 0.f;

    const float* dtp = g_dtv + (size_t)b * 256 * DINNER + d;
    const float* up  = g_u   + (size_t)b * 256 * DINNER + d;
    const float* zp  = g_xz  + (size_t)b * 256 * (2 * DINNER) + DINNER + d;
    const float* bc  = g_dbl + (size_t)b * 256 * DBL_LD;
    const int cj = (d >> 5) * 64 + (d & 31);

    for (int l = 0; l < 256; l++) {
        float dt = dtp[(size_t)l * DINNER];
        float u  = up [(size_t)l * DINNER];
        const float4* bcrow = reinterpret_cast<const float4*>(bc + (size_t)l * DBL_LD + 84);
        float4 Bv0 = bcrow[0], Bv1 = bcrow[1], Bv2 = bcrow[2], Bv3 = bcrow[3];
        float4 Cv0 = bcrow[4], Cv1 = bcrow[5], Cv2 = bcrow[6], Cv3 = bcrow[7];
        float Bm[16] = {Bv0.x,Bv0.y,Bv0.z,Bv0.w, Bv1.x,Bv1.y,Bv1.z,Bv1.w,
                        Bv2.x,Bv2.y,Bv2.z,Bv2.w, Bv3.x,Bv3.y,Bv3.z,Bv3.w};
        float Cm[16] = {Cv0.x,Cv0.y,Cv0.z,Cv0.w, Cv1.x,Cv1.y,Cv1.z,Cv1.w,
                        Cv2.x,Cv2.y,Cv2.z,Cv2.w, Cv3.x,Cv3.y,Cv3.z,Cv3.w};
        float xbu = dt * u;
        float y = 0.f;
#pragma unroll
        for (int n = 0; n < DSTATE; n++) {
            float dA = __expf(dt * A[n]);
            h[n] = dA * h[n] + xbu * Bm[n];
            y += h[n] * Cm[n];
        }
        float z = zp[(size_t)l * (2 * DINNER)];
        float sil = z / (1.f + __expf(-z));
        float v = (y + u * Dd) * sil;
        size_t hb = ((size_t)(b * 256 + l) * 81) * 64 + cj;
        __nv_bfloat16 hi = __float2bfloat16(v);
        g_yshl[hb] = hi;
        g_yshl[hb + 32] = __float2bfloat16(v - __bfloat162float(hi));
    }
}

// ================= launch =================
extern "C" void kernel_launch(void* const* d_in, const int* in_sizes, int n_in,
                              void* d_out, int out_size) {
    (void)in_sizes; (void)n_in; (void)out_size;
    const float* x         = (const float*)d_in[0];
    const float* pc_emb    = (const float*)d_in[1];
    const float* conv_w    = (const float*)d_in[2];
    const float* bn_gamma  = (const float*)d_in[3];
    const float* bn_beta   = (const float*)d_in[4];
    const float* bn_mean   = (const float*)d_in[5];
    const float* bn_var    = (const float*)d_in[6];
    const float* in_proj_w = (const float*)d_in[7];
    const float* conv1d_w  = (const float*)d_in[8];
    const float* conv1d_b  = (const float*)d_in[9];
    const float* x_proj_w  = (const float*)d_in[10];
    const float* dt_proj_w = (const float*)d_in[11];
    const float* dt_proj_b = (const float*)d_in[12];
    const float* A_log     = (const float*)d_in[13];
    const float* Dvec      = (const float*)d_in[14];
    const float* out_proj_w= (const float*)d_in[15];
    float* out = (float*)d_out;

    float *p_seq, *p_tmp0, *p_pooled, *p_yp, *p_xz, *p_dbl, *p_dtv, *p_bn;
    __nv_bfloat16 *p_seqhl, *p_winhl, *p_uhl, *p_xwhl, *p_dblhl, *p_dtwhl, *p_yshl, *p_wouthl;
    __nv_bfloat16 *p_combhl, *p_cw0hl;
    cudaGetSymbolAddress((void**)&p_seq,    g_seq);
    cudaGetSymbolAddress((void**)&p_tmp0,   g_tmp0);
    cudaGetSymbolAddress((void**)&p_pooled, g_pooled);
    cudaGetSymbolAddress((void**)&p_yp,     g_yp);
    cudaGetSymbolAddress((void**)&p_xz,     g_xz);
    cudaGetSymbolAddress((void**)&p_dbl,    g_dbl);
    cudaGetSymbolAddress((void**)&p_dtv,    g_dtv);
    cudaGetSymbolAddress((void**)&p_bn,     g_bn);
    cudaGetSymbolAddress((void**)&p_seqhl,  g_seqhl);
    cudaGetSymbolAddress((void**)&p_winhl,  g_winhl);
    cudaGetSymbolAddress((void**)&p_uhl,    g_uhl);
    cudaGetSymbolAddress((void**)&p_xwhl,   g_xwhl);
    cudaGetSymbolAddress((void**)&p_dblhl,  g_dblhl);
    cudaGetSymbolAddress((void**)&p_dtwhl,  g_dtwhl);
    cudaGetSymbolAddress((void**)&p_yshl,   g_yshl);
    cudaGetSymbolAddress((void**)&p_wouthl, g_wouthl);
    cudaGetSymbolAddress((void**)&p_combhl, g_combhl);
    cudaGetSymbolAddress((void**)&p_cw0hl,  g_cw0hl);

    cudaFuncSetAttribute(wgemm2<0>, cudaFuncAttributeMaxDynamicSharedMemorySize, WS2);
    cudaFuncSetAttribute(wgemm2<1>, cudaFuncAttributeMaxDynamicSharedMemorySize, WS2);
    cudaFuncSetAttribute(wgemm2<2>, cudaFuncAttributeMaxDynamicSharedMemorySize, WS2);
    cudaFuncSetAttribute(wgemm2<3>, cudaFuncAttributeMaxDynamicSharedMemorySize, WS2);
    cudaFuncSetAttribute(wgemm2<4>, cudaFuncAttributeMaxDynamicSharedMemorySize, WS2);

    // weight converts (independent of data path)
    k_cvt<<<(5248*41*16 + 255)/256, 256>>>(in_proj_w,  p_winhl,  5128, 1282, 1282, 41, 5248*41*16);
    k_cvt<<<(1408*81*16 + 255)/256, 256>>>(out_proj_w, p_wouthl, 1282, 2564, 2564, 81, 1408*81*16);
    k_cvt<<<(128*81*16  + 255)/256, 256>>>(x_proj_w,   p_xwhl,    113, 2564, 2564, 81, 128*81*16);
    k_cvt<<<(2688*3*16  + 255)/256, 256>>>(dt_proj_w,  p_dtwhl,  2564,   81,   81,  3, 2688*3*16);
    k_cvt<<<(128*25*16  + 255)/256, 256>>>(conv_w,     p_cw0hl,   128,  770,  770, 25, 128*25*16);

    // PPM
    k_bnprep<<<1, 512>>>(bn_gamma, bn_beta, bn_mean, bn_var);
    k_build<<<dim3(64, 25, 8), dim3(32, 32)>>>(x, pc_emb);
    // cbr0 on tensor cores: comb cols 0..770 -> hi/lo (25 chunks), BN+ReLU6 -> g_tmp0
    k_cvt<<<(MSEQ*25*16 + 255)/256, 256>>>(p_seq, p_combhl, MSEQ, 770, LDSEQ, 25, MSEQ*25*16);
    wgemm2<4><<<dim3(1, 128), 256, WS2>>>(p_combhl, p_cw0hl, p_tmp0, 128, 128, 25, p_bn);
    k_reduce0<<<64, 128>>>();
    k_pool<<<dim3(64, 275), 256>>>();
    sgemm<1><<<dim3(1, 13), 256>>>(p_pooled, conv_w + 1 * 128 * COMBC, p_yp,
                                   1600, 128, COMBC, COMBC, COMBC, 128,
                                   p_bn + 128, p_bn + 512 + 128);
    sgemm<1><<<dim3(1, 41), 256>>>(p_pooled + (size_t)1600 * COMBC, conv_w + 2 * 128 * COMBC,
                                   p_yp + (size_t)1600 * 128,
                                   5184, 128, COMBC, COMBC, COMBC, 128,
                                   p_bn + 256, p_bn + 512 + 256);
    sgemm<1><<<dim3(1, 85), 256>>>(p_pooled + (size_t)6784 * COMBC, conv_w + 3 * 128 * COMBC,
                                   p_yp + (size_t)6784 * 128,
                                   10816, 128, COMBC, COMBC, COMBC, 128,
                                   p_bn + 384, p_bn + 512 + 384);
    k_assemble<<<MSEQ, 512>>>();
    k_cvt<<<(MSEQ*41*16 + 255)/256, 256>>>(p_seq, p_seqhl, MSEQ, 1312, LDSEQ, 41, MSEQ*41*16);

    // Mamba
    wgemm2<0><<<dim3(41, 128), 256, WS2>>>(p_seqhl, p_winhl, p_xz, 5128, 5128, 41, nullptr);
    k_conv1d<<<dim3(64, 11), 256>>>(conv1d_w, conv1d_b);
    wgemm2<2><<<dim3(1, 128),  256, WS2>>>(p_uhl, p_xwhl, p_dbl, 113, 0, 81, nullptr);
    wgemm2<3><<<dim3(21, 128), 256, WS2>>>(p_dblhl, p_dtwhl, p_dtv, DINNER, 0, 3, dt_proj_b);
    k_scan<<<dim3(11, 64), 256>>>(A_log, Dvec);
    wgemm2<1><<<dim3(11, 128), 256, WS2>>>(p_yshl, p_wouthl, out, DMODEL, 0, 81, nullptr);
}